// round 2
// baseline (speedup 1.0000x reference)
#include <cuda_runtime.h>
#include <math.h>

// Problem constants
#define M_ROWS   4096      // B*S
#define NTDIM    1024
#define NGROUP   64        // B*heads
#define DPH      64
#define SEQ      1024      // rows per head-group after flat reshape
#define ATT_SCALE 0.03125f // 1024^-0.5
#define LNEPS    1e-5f

// Scratch (allocation-free rule: __device__ globals)
__device__ float g_q[M_ROWS * NTDIM];
__device__ float g_k[M_ROWS * NTDIM];
__device__ float g_v[M_ROWS * NTDIM];
__device__ float g_ctx[M_ROWS * NTDIM];

// ---------------------------------------------------------------------------
// Kernel 0: zero the at_sum_sum region of d_out (poisoned 0xAA each replay)
// ---------------------------------------------------------------------------
__global__ void zero_sums_kernel(float* __restrict__ sums) {
    sums[blockIdx.x * 256 + threadIdx.x] = 0.0f;
}

// ---------------------------------------------------------------------------
// Kernel 1: QKV projection.  C = X * W^T + b   (X [4096,1024], W [1024,1024])
// grid (8 nblk, 32 mblk, 3 matrices), 256 threads, 128x128 tile, 8x8/thread.
// ---------------------------------------------------------------------------
__global__ __launch_bounds__(256) void qkv_kernel(
    const float* __restrict__ x,
    const float* __restrict__ Wq, const float* __restrict__ bq,
    const float* __restrict__ Wk, const float* __restrict__ bk,
    const float* __restrict__ Wv, const float* __restrict__ bv)
{
    const float* W; const float* bias; float* out;
    if (blockIdx.z == 0)      { W = Wq; bias = bq; out = g_q; }
    else if (blockIdx.z == 1) { W = Wk; bias = bk; out = g_k; }
    else                      { W = Wv; bias = bv; out = g_v; }

    __shared__ float As[16][132];   // k-major: As[k][m]
    __shared__ float Bs[16][132];   // k-major: Bs[k][n]

    const int m0 = blockIdx.y * 128;
    const int n0 = blockIdx.x * 128;
    const int t  = threadIdx.x;
    const int tx = t & 15;          // 0..15 -> n frag
    const int ty = t >> 4;          // 0..15 -> m frag

    const int lrow = t >> 2;        // 0..63
    const int lk4  = (t & 3) * 4;   // 0,4,8,12

    float acc[8][8];
    #pragma unroll
    for (int i = 0; i < 8; i++)
        #pragma unroll
        for (int j = 0; j < 8; j++) acc[i][j] = 0.0f;

    for (int k0 = 0; k0 < NTDIM; k0 += 16) {
        #pragma unroll
        for (int h = 0; h < 2; h++) {
            int row = lrow + h * 64;
            float4 va = *reinterpret_cast<const float4*>(&x[(size_t)(m0 + row) * NTDIM + k0 + lk4]);
            As[lk4 + 0][row] = va.x; As[lk4 + 1][row] = va.y;
            As[lk4 + 2][row] = va.z; As[lk4 + 3][row] = va.w;
            float4 vb = *reinterpret_cast<const float4*>(&W[(size_t)(n0 + row) * NTDIM + k0 + lk4]);
            Bs[lk4 + 0][row] = vb.x; Bs[lk4 + 1][row] = vb.y;
            Bs[lk4 + 2][row] = vb.z; Bs[lk4 + 3][row] = vb.w;
        }
        __syncthreads();

        #pragma unroll 8
        for (int k = 0; k < 16; k++) {
            float4 a0 = *reinterpret_cast<const float4*>(&As[k][ty * 4]);
            float4 a1 = *reinterpret_cast<const float4*>(&As[k][64 + ty * 4]);
            float4 b0 = *reinterpret_cast<const float4*>(&Bs[k][tx * 4]);
            float4 b1 = *reinterpret_cast<const float4*>(&Bs[k][64 + tx * 4]);
            float a[8] = {a0.x, a0.y, a0.z, a0.w, a1.x, a1.y, a1.z, a1.w};
            float b[8] = {b0.x, b0.y, b0.z, b0.w, b1.x, b1.y, b1.z, b1.w};
            #pragma unroll
            for (int i = 0; i < 8; i++)
                #pragma unroll
                for (int j = 0; j < 8; j++) acc[i][j] += a[i] * b[j];
        }
        __syncthreads();
    }

    #pragma unroll
    for (int ih = 0; ih < 2; ih++) {
        #pragma unroll
        for (int r = 0; r < 4; r++) {
            int m = m0 + ih * 64 + ty * 4 + r;
            #pragma unroll
            for (int jh = 0; jh < 2; jh++) {
                int n = n0 + jh * 64 + tx * 4;
                float4 o;
                o.x = acc[ih * 4 + r][jh * 4 + 0] + bias[n + 0];
                o.y = acc[ih * 4 + r][jh * 4 + 1] + bias[n + 1];
                o.z = acc[ih * 4 + r][jh * 4 + 2] + bias[n + 2];
                o.w = acc[ih * 4 + r][jh * 4 + 3] + bias[n + 3];
                *reinterpret_cast<float4*>(&out[(size_t)m * NTDIM + n]) = o;
            }
        }
    }
}

// ---------------------------------------------------------------------------
// Kernel 2: attention per (row-block, head-group). Two-pass softmax so the
// normalized column sums (at_sum_sum) and context can stream over K/V tiles.
// ---------------------------------------------------------------------------
// dynamic smem layout (floats)
#define SM_QST   0                     // [64][132]  k-major swizzled Q
#define SM_KST   8448                  // [64][132]
#define SM_VS    16896                 // [128][68]  row-major V
#define SM_PST   25600                 // [128][132] col-major swizzled P
#define SM_RS    42496                 // [128] row sums
#define SM_CS    42624                 // [128] col sums
#define ATT_SMEM_FLOATS 42752
#define ATT_SMEM_BYTES  (ATT_SMEM_FLOATS * 4)

__device__ __forceinline__ int swz4(int idx) { return ((idx >> 2) & 7) << 2; }

__global__ __launch_bounds__(256) void attn_kernel(float* __restrict__ sums)
{
    extern __shared__ float sm[];
    float* QsT = sm + SM_QST;
    float* KsT = sm + SM_KST;
    float* Vs  = sm + SM_VS;
    float* PsT = sm + SM_PST;
    float* rs  = sm + SM_RS;
    float* cs  = sm + SM_CS;

    const int g  = blockIdx.y;        // head-group 0..63
    const int ib = blockIdx.x;        // row block 0..7
    const float* __restrict__ Qh = g_q + (size_t)g * (SEQ * DPH);
    const float* __restrict__ Kh = g_k + (size_t)g * (SEQ * DPH);
    const float* __restrict__ Vh = g_v + (size_t)g * (SEQ * DPH);

    const int t  = threadIdx.x;
    const int tx = t & 15;
    const int ty = t >> 4;
    const int r0 = ty * 4;
    const int c0 = tx * 4;

    // stage Q block (rows ib*128..+127) k-major with swizzle
    #pragma unroll
    for (int it = 0; it < 8; it++) {
        int fid = t + it * 256;
        int row = fid >> 4;
        int d   = (fid & 15) * 4;
        float4 v = *reinterpret_cast<const float4*>(&Qh[(size_t)(ib * 128 + row) * DPH + d]);
        QsT[(d + 0) * 132 + (row ^ swz4(d + 0))] = v.x;
        QsT[(d + 1) * 132 + (row ^ swz4(d + 1))] = v.y;
        QsT[(d + 2) * 132 + (row ^ swz4(d + 2))] = v.z;
        QsT[(d + 3) * 132 + (row ^ swz4(d + 3))] = v.w;
    }
    if (t < 128) rs[t] = 0.0f;
    __syncthreads();

    // ---------------- PASS 1: row sums of E = exp(relu(z/32)) --------------
    for (int jb = 0; jb < 8; jb++) {
        #pragma unroll
        for (int it = 0; it < 8; it++) {
            int fid = t + it * 256;
            int row = fid >> 4;
            int d   = (fid & 15) * 4;
            float4 v = *reinterpret_cast<const float4*>(&Kh[(size_t)(jb * 128 + row) * DPH + d]);
            KsT[(d + 0) * 132 + (row ^ swz4(d + 0))] = v.x;
            KsT[(d + 1) * 132 + (row ^ swz4(d + 1))] = v.y;
            KsT[(d + 2) * 132 + (row ^ swz4(d + 2))] = v.z;
            KsT[(d + 3) * 132 + (row ^ swz4(d + 3))] = v.w;
        }
        __syncthreads();

        float z[8][8];
        #pragma unroll
        for (int i = 0; i < 8; i++)
            #pragma unroll
            for (int j = 0; j < 8; j++) z[i][j] = 0.0f;

        #pragma unroll 8
        for (int d = 0; d < 64; d++) {
            int sw = swz4(d);
            const float* qrow = &QsT[d * 132];
            const float* krow = &KsT[d * 132];
            float4 a0 = *reinterpret_cast<const float4*>(&qrow[r0 ^ sw]);
            float4 a1 = *reinterpret_cast<const float4*>(&qrow[(64 + r0) ^ sw]);
            float4 b0 = *reinterpret_cast<const float4*>(&krow[c0 ^ sw]);
            float4 b1 = *reinterpret_cast<const float4*>(&krow[(64 + c0) ^ sw]);
            float a[8] = {a0.x, a0.y, a0.z, a0.w, a1.x, a1.y, a1.z, a1.w};
            float b[8] = {b0.x, b0.y, b0.z, b0.w, b1.x, b1.y, b1.z, b1.w};
            #pragma unroll
            for (int i = 0; i < 8; i++)
                #pragma unroll
                for (int j = 0; j < 8; j++) z[i][j] += a[i] * b[j];
        }

        #pragma unroll
        for (int i = 0; i < 8; i++) {
            float s = 0.0f;
            #pragma unroll
            for (int j = 0; j < 8; j++)
                s += __expf(fmaxf(z[i][j] * ATT_SCALE, 0.0f));
            int row = (i < 4) ? (r0 + i) : (64 + r0 + i - 4);
            atomicAdd(&rs[row], s);
        }
        __syncthreads();
    }

    float rinv[8];
    #pragma unroll
    for (int i = 0; i < 8; i++) {
        int row = (i < 4) ? (r0 + i) : (64 + r0 + i - 4);
        rinv[i] = 1.0f / rs[row];
    }

    // ---------------- PASS 2: P = E/rowsum, colsums, O = P @ V -------------
    float o[8][4];
    #pragma unroll
    for (int i = 0; i < 8; i++)
        #pragma unroll
        for (int c = 0; c < 4; c++) o[i][c] = 0.0f;

    for (int jb = 0; jb < 8; jb++) {
        #pragma unroll
        for (int it = 0; it < 8; it++) {
            int fid = t + it * 256;
            int row = fid >> 4;
            int d   = (fid & 15) * 4;
            float4 vk = *reinterpret_cast<const float4*>(&Kh[(size_t)(jb * 128 + row) * DPH + d]);
            KsT[(d + 0) * 132 + (row ^ swz4(d + 0))] = vk.x;
            KsT[(d + 1) * 132 + (row ^ swz4(d + 1))] = vk.y;
            KsT[(d + 2) * 132 + (row ^ swz4(d + 2))] = vk.z;
            KsT[(d + 3) * 132 + (row ^ swz4(d + 3))] = vk.w;
            float4 vv = *reinterpret_cast<const float4*>(&Vh[(size_t)(jb * 128 + row) * DPH + d]);
            *reinterpret_cast<float4*>(&Vs[row * 68 + d]) = vv;
        }
        if (t < 128) cs[t] = 0.0f;
        __syncthreads();

        float z[8][8];
        #pragma unroll
        for (int i = 0; i < 8; i++)
            #pragma unroll
            for (int j = 0; j < 8; j++) z[i][j] = 0.0f;

        #pragma unroll 8
        for (int d = 0; d < 64; d++) {
            int sw = swz4(d);
            const float* qrow = &QsT[d * 132];
            const float* krow = &KsT[d * 132];
            float4 a0 = *reinterpret_cast<const float4*>(&qrow[r0 ^ sw]);
            float4 a1 = *reinterpret_cast<const float4*>(&qrow[(64 + r0) ^ sw]);
            float4 b0 = *reinterpret_cast<const float4*>(&krow[c0 ^ sw]);
            float4 b1 = *reinterpret_cast<const float4*>(&krow[(64 + c0) ^ sw]);
            float a[8] = {a0.x, a0.y, a0.z, a0.w, a1.x, a1.y, a1.z, a1.w};
            float b[8] = {b0.x, b0.y, b0.z, b0.w, b1.x, b1.y, b1.z, b1.w};
            #pragma unroll
            for (int i = 0; i < 8; i++)
                #pragma unroll
                for (int j = 0; j < 8; j++) z[i][j] += a[i] * b[j];
        }

        #pragma unroll
        for (int j = 0; j < 8; j++) {
            int col = (j < 4) ? (c0 + j) : (64 + c0 + j - 4);
            int csw = swz4(col);
            float s = 0.0f;
            #pragma unroll
            for (int i = 0; i < 8; i++) {
                float p = __expf(fmaxf(z[i][j] * ATT_SCALE, 0.0f)) * rinv[i];
                s += p;
                int row = (i < 4) ? (r0 + i) : (64 + r0 + i - 4);
                PsT[col * 132 + (row ^ csw)] = p;
            }
            atomicAdd(&cs[col], s);
        }
        __syncthreads();

        #pragma unroll 4
        for (int j = 0; j < 128; j++) {
            int jsw = swz4(j);
            const float* prow = &PsT[j * 132];
            float4 pa = *reinterpret_cast<const float4*>(&prow[r0 ^ jsw]);
            float4 pb = *reinterpret_cast<const float4*>(&prow[(64 + r0) ^ jsw]);
            float4 vv = *reinterpret_cast<const float4*>(&Vs[j * 68 + c0]);
            float p[8] = {pa.x, pa.y, pa.z, pa.w, pb.x, pb.y, pb.z, pb.w};
            #pragma unroll
            for (int i = 0; i < 8; i++) {
                o[i][0] += p[i] * vv.x;
                o[i][1] += p[i] * vv.y;
                o[i][2] += p[i] * vv.z;
                o[i][3] += p[i] * vv.w;
            }
        }

        if (t < 128) atomicAdd(&sums[g * 1024 + jb * 128 + t], cs[t]);
        __syncthreads();
    }

    // write context
    float* __restrict__ Ch = g_ctx + (size_t)g * (SEQ * DPH);
    #pragma unroll
    for (int i = 0; i < 8; i++) {
        int row = ib * 128 + ((i < 4) ? (r0 + i) : (64 + r0 + i - 4));
        float4 ov; ov.x = o[i][0]; ov.y = o[i][1]; ov.z = o[i][2]; ov.w = o[i][3];
        *reinterpret_cast<float4*>(&Ch[(size_t)row * DPH + c0]) = ov;
    }
}

// ---------------------------------------------------------------------------
// Kernel 3: residual + LayerNorm.  One 256-thread CTA per row (4096 rows).
// ---------------------------------------------------------------------------
__global__ __launch_bounds__(256) void ln_kernel(
    const float* __restrict__ x,
    const float* __restrict__ gamma,
    const float* __restrict__ beta,
    float* __restrict__ out)
{
    const int row = blockIdx.x;
    const int t = threadIdx.x;
    const float* xr = x + (size_t)row * NTDIM;
    const float* cr = g_ctx + (size_t)row * NTDIM;

    float h[4];
    float s = 0.0f, sq = 0.0f;
    #pragma unroll
    for (int i = 0; i < 4; i++) {
        int idx = t + i * 256;
        h[i] = xr[idx] + cr[idx];
        s  += h[i];
        sq += h[i] * h[i];
    }
    #pragma unroll
    for (int off = 16; off; off >>= 1) {
        s  += __shfl_xor_sync(0xffffffffu, s,  off);
        sq += __shfl_xor_sync(0xffffffffu, sq, off);
    }
    __shared__ float rsum[8], rsq[8];
    int warp = t >> 5, lane = t & 31;
    if (lane == 0) { rsum[warp] = s; rsq[warp] = sq; }
    __syncthreads();
    float S = 0.0f, SQ = 0.0f;
    #pragma unroll
    for (int w = 0; w < 8; w++) { S += rsum[w]; SQ += rsq[w]; }
    float mean = S * (1.0f / NTDIM);
    float var  = SQ * (1.0f / NTDIM) - mean * mean;
    float inv  = rsqrtf(var + LNEPS);
    float* orow = out + (size_t)row * NTDIM;
    #pragma unroll
    for (int i = 0; i < 4; i++) {
        int idx = t + i * 256;
        orow[idx] = (h[i] - mean) * inv * gamma[idx] + beta[idx];
    }
}

// ---------------------------------------------------------------------------
extern "C" void kernel_launch(void* const* d_in, const int* in_sizes, int n_in,
                              void* d_out, int out_size)
{
    const float* x     = (const float*)d_in[0];
    const float* Wq    = (const float*)d_in[1];
    const float* bq    = (const float*)d_in[2];
    const float* Wk    = (const float*)d_in[3];
    const float* bk    = (const float*)d_in[4];
    const float* Wv    = (const float*)d_in[5];
    const float* bv    = (const float*)d_in[6];
    const float* gamma = (const float*)d_in[7];
    const float* beta  = (const float*)d_in[8];

    float* out  = (float*)d_out;
    float* sums = out + (size_t)M_ROWS * NTDIM;   // [64,1024] at_sum_sum region

    cudaFuncSetAttribute(attn_kernel,
                         cudaFuncAttributeMaxDynamicSharedMemorySize,
                         ATT_SMEM_BYTES);

    zero_sums_kernel<<<256, 256>>>(sums);

    dim3 gq(8, 32, 3);
    qkv_kernel<<<gq, 256>>>(x, Wq, bq, Wk, bk, Wv, bv);

    dim3 ga(8, 64);
    attn_kernel<<<ga, 256, ATT_SMEM_BYTES>>>(sums);

    ln_kernel<<<M_ROWS, 256>>>(x, gamma, beta, out);
}

// round 4
// speedup vs baseline: 1.5572x; 1.5572x over previous
#include <cuda_runtime.h>
#include <cuda_bf16.h>
#include <cstdint>
#include <math.h>

// Problem constants
#define M_ROWS   4096      // B*S
#define NTDIM    1024
#define NGROUP   64        // B*heads
#define DPH      64
#define SEQ      1024
#define ATT_SCALE 0.03125f // 1024^-0.5
#define LNEPS    1e-5f

// Scratch (allocation-free rule: __device__ globals)
__device__ float g_q[M_ROWS * NTDIM];
__device__ float g_k[M_ROWS * NTDIM];
__device__ float g_v[M_ROWS * NTDIM];
__device__ float g_ctx[M_ROWS * NTDIM];
__device__ __nv_bfloat16 g_xh[M_ROWS * NTDIM];
__device__ __nv_bfloat16 g_xl[M_ROWS * NTDIM];
__device__ __nv_bfloat16 g_wh[3 * NTDIM * NTDIM];
__device__ __nv_bfloat16 g_wl[3 * NTDIM * NTDIM];
__device__ __nv_bfloat16 g_e[67108864];   // 64 x 1024 x 1024 bf16 E cache

// ===========================================================================
// PTX helpers: mma.sync (HMMA) + ldmatrix + cp.async  (plain sm_80+ PTX)
// ===========================================================================
__device__ __forceinline__ uint32_t smem_u32(const void* p) {
    uint32_t a;
    asm("{ .reg .u64 t; cvta.to.shared.u64 t, %1; cvt.u32.u64 %0, t; }" : "=r"(a) : "l"(p));
    return a;
}
__device__ __forceinline__ void ldsm_x4(uint32_t* r, uint32_t addr) {
    asm volatile("ldmatrix.sync.aligned.m8n8.x4.shared.b16 {%0,%1,%2,%3}, [%4];"
                 : "=r"(r[0]), "=r"(r[1]), "=r"(r[2]), "=r"(r[3]) : "r"(addr));
}
__device__ __forceinline__ void mma_bf16(float* d, const uint32_t* a,
                                         uint32_t b0, uint32_t b1) {
    asm volatile(
        "mma.sync.aligned.m16n8k16.row.col.f32.bf16.bf16.f32 "
        "{%0,%1,%2,%3}, {%4,%5,%6,%7}, {%8,%9}, {%0,%1,%2,%3};"
        : "+f"(d[0]), "+f"(d[1]), "+f"(d[2]), "+f"(d[3])
        : "r"(a[0]), "r"(a[1]), "r"(a[2]), "r"(a[3]), "r"(b0), "r"(b1));
}
__device__ __forceinline__ void cpa16(uint32_t dst, const void* src) {
    size_t gp;
    asm("cvta.to.global.u64 %0, %1;" : "=l"(gp) : "l"(src));
    asm volatile("cp.async.cg.shared.global [%0], [%1], 16;" :: "r"(dst), "l"(gp) : "memory");
}
__device__ __forceinline__ void cpa_commit() {
    asm volatile("cp.async.commit_group;" ::: "memory");
}
__device__ __forceinline__ void cpa_wait0() {
    asm volatile("cp.async.wait_group 0;" ::: "memory");
}

// ---------------------------------------------------------------------------
// Kernel 0: zero the at_sum_sum region of d_out
// ---------------------------------------------------------------------------
__global__ void zero_sums_kernel(float* __restrict__ sums) {
    sums[blockIdx.x * 256 + threadIdx.x] = 0.0f;
}

// ---------------------------------------------------------------------------
// Kernel 0b: fp32 -> bf16 hi/lo split.  sel: 0 = x, 1..3 = Wq/Wk/Wv
// ---------------------------------------------------------------------------
__global__ __launch_bounds__(256) void cvt_kernel(const float* __restrict__ src, int sel) {
    __nv_bfloat16 *hi, *lo;
    if (sel == 0) { hi = g_xh; lo = g_xl; }
    else { hi = g_wh + (size_t)(sel - 1) * 1048576; lo = g_wl + (size_t)(sel - 1) * 1048576; }
    size_t i = ((size_t)blockIdx.x * 256 + threadIdx.x) * 4;
    float4 v = *reinterpret_cast<const float4*>(src + i);
    __nv_bfloat16 h0 = __float2bfloat16(v.x);
    __nv_bfloat16 h1 = __float2bfloat16(v.y);
    __nv_bfloat16 h2 = __float2bfloat16(v.z);
    __nv_bfloat16 h3 = __float2bfloat16(v.w);
    __nv_bfloat16 l0 = __float2bfloat16(v.x - __bfloat162float(h0));
    __nv_bfloat16 l1 = __float2bfloat16(v.y - __bfloat162float(h1));
    __nv_bfloat16 l2 = __float2bfloat16(v.z - __bfloat162float(h2));
    __nv_bfloat16 l3 = __float2bfloat16(v.w - __bfloat162float(h3));
    union { __nv_bfloat162 h2v[2]; uint2 u; } uh, ul;
    uh.h2v[0] = __halves2bfloat162(h0, h1);
    uh.h2v[1] = __halves2bfloat162(h2, h3);
    ul.h2v[0] = __halves2bfloat162(l0, l1);
    ul.h2v[1] = __halves2bfloat162(l2, l3);
    *reinterpret_cast<uint2*>(hi + i) = uh.u;
    *reinterpret_cast<uint2*>(lo + i) = ul.u;
}

// ---------------------------------------------------------------------------
// Kernel 1: QKV projection via mma.sync bf16 (split hi/lo x3, fp32 accum).
// C[4096,1024] = X @ W^T + b.  CTA tile 128x128, k-stage 64, double-buffered
// cp.async, SW128-swizzled smem, ldmatrix fragments.
// grid (8 ntile, 32 mtile, 3 matrices), 256 threads (8 warps, 4m x 2n).
// Smem per stage: Ah/Al/Bh/Bl each 128x64 bf16 = 16KB -> 64KB; x2 = 128KB.
// ---------------------------------------------------------------------------
#define QST_AH 0
#define QST_AL 16384
#define QST_BH 32768
#define QST_BL 49152
#define QST_SZ 65536
#define QKV_SMEM (2 * QST_SZ)

__global__ __launch_bounds__(256) void qkv_mma_kernel(
    const float* __restrict__ bq, const float* __restrict__ bk, const float* __restrict__ bv)
{
    extern __shared__ char smc[];
    const uint32_t smb = smem_u32(smc);
    const int t = threadIdx.x;
    const int w = t >> 5;
    const int l = t & 31;
    const int z = blockIdx.z;
    const __nv_bfloat16* __restrict__ Wh = g_wh + (size_t)z * NTDIM * NTDIM;
    const __nv_bfloat16* __restrict__ Wl = g_wl + (size_t)z * NTDIM * NTDIM;
    const float* bias = (z == 0) ? bq : (z == 1) ? bk : bv;
    float* out = (z == 0) ? g_q : (z == 1) ? g_k : g_v;
    const int m0 = blockIdx.y * 128;
    const int n0 = blockIdx.x * 128;
    const int wr0 = (w >> 1) * 32;   // warp m-origin (warptile 32x64)
    const int wn0 = (w & 1) * 64;    // warp n-origin

    // staging coordinates for this thread (4 chunks of 16B per matrix)
    const int sr[4] = { (t + 0) >> 3, (t + 256) >> 3, (t + 512) >> 3, (t + 768) >> 3 };
    const int sc = t & 7;

    float acc[2][8][4];
    #pragma unroll
    for (int a = 0; a < 2; a++)
        #pragma unroll
        for (int b = 0; b < 8; b++)
            #pragma unroll
            for (int c = 0; c < 4; c++) acc[a][b][c] = 0.0f;

    // issue cp.async loads for stage s into buffer buf
    auto issue_stage = [&](int s, int buf) {
        const int k0 = s * 64;
        const uint32_t sb = smb + buf * QST_SZ;
        #pragma unroll
        for (int i = 0; i < 4; i++) {
            const int r = sr[i];
            const uint32_t doff = r * 128 + (((sc ^ (r & 7)) << 4));
            const size_t aoff = (size_t)(m0 + r) * NTDIM + k0 + sc * 8;
            const size_t boff = (size_t)(n0 + r) * NTDIM + k0 + sc * 8;
            cpa16(sb + QST_AH + doff, g_xh + aoff);
            cpa16(sb + QST_AL + doff, g_xl + aoff);
            cpa16(sb + QST_BH + doff, Wh + boff);
            cpa16(sb + QST_BL + doff, Wl + boff);
        }
        cpa_commit();
    };

    issue_stage(0, 0);

    for (int s = 0; s < 16; s++) {
        cpa_wait0();
        __syncthreads();
        if (s < 15) issue_stage(s + 1, (s + 1) & 1);
        const uint32_t bb = smb + (s & 1) * QST_SZ;

        #pragma unroll
        for (int kt = 0; kt < 4; kt++) {
            const int chunk = kt * 2 + (l >> 4);
            uint32_t ah[2][4], al[2][4];
            #pragma unroll
            for (int mf = 0; mf < 2; mf++) {
                const int r = wr0 + mf * 16 + (l & 15);
                const uint32_t ad = bb + r * 128 + (((chunk ^ (r & 7)) << 4));
                ldsm_x4(ah[mf], ad + QST_AH);
                ldsm_x4(al[mf], ad + QST_AL);
            }
            #pragma unroll
            for (int nq = 0; nq < 4; nq++) {
                const int rr = wn0 + nq * 16 + (l & 15);
                const uint32_t bd = bb + rr * 128 + (((chunk ^ (rr & 7)) << 4));
                uint32_t bh[4], bl[4];
                ldsm_x4(bh, bd + QST_BH);
                ldsm_x4(bl, bd + QST_BL);
                #pragma unroll
                for (int mf = 0; mf < 2; mf++) {
                    #pragma unroll
                    for (int nh = 0; nh < 2; nh++) {
                        float* d = acc[mf][nq * 2 + nh];
                        mma_bf16(d, ah[mf], bh[nh], bh[2 + nh]);
                        mma_bf16(d, ah[mf], bl[nh], bl[2 + nh]);
                        mma_bf16(d, al[mf], bh[nh], bh[2 + nh]);
                    }
                }
            }
        }
    }

    // epilogue: acc + bias -> fp32 out
    const int lr = l >> 2;
    const int lc = (l & 3) * 2;
    #pragma unroll
    for (int mf = 0; mf < 2; mf++) {
        #pragma unroll
        for (int nf = 0; nf < 8; nf++) {
            const int col = n0 + wn0 + nf * 8 + lc;
            const int row = m0 + wr0 + mf * 16 + lr;
            const float* d = acc[mf][nf];
            float2 o0, o1;
            o0.x = d[0] + bias[col];
            o0.y = d[1] + bias[col + 1];
            o1.x = d[2] + bias[col];
            o1.y = d[3] + bias[col + 1];
            *reinterpret_cast<float2*>(out + (size_t)row * NTDIM + col) = o0;
            *reinterpret_cast<float2*>(out + (size_t)(row + 8) * NTDIM + col) = o1;
        }
    }
}

// ---------------------------------------------------------------------------
// Kernel 2: attention. Pass 1 computes z = QK^T once, stores E=exp(relu(z/32))
// as bf16 to global and accumulates row sums (of the rounded E). Pass 2 reads
// E back, normalizes, accumulates column sums, computes O = P @ V.
// ---------------------------------------------------------------------------
#define SM_QST   0                     // [64][132]  k-major swizzled Q
#define SM_KST   8448                  // [64][132]
#define SM_VS    16896                 // [128][68]  row-major V
#define SM_PST   25600                 // [128][132] col-major swizzled P
#define SM_RS    42496                 // [128] row sums
#define SM_CS    42624                 // [128] col sums
#define ATT_SMEM_FLOATS 42752
#define ATT_SMEM_BYTES  (ATT_SMEM_FLOATS * 4)

__device__ __forceinline__ int swz4(int idx) { return ((idx >> 2) & 7) << 2; }

__global__ __launch_bounds__(256) void attn_kernel(float* __restrict__ sums)
{
    extern __shared__ float sm[];
    float* QsT = sm + SM_QST;
    float* KsT = sm + SM_KST;
    float* Vs  = sm + SM_VS;
    float* PsT = sm + SM_PST;
    float* rs  = sm + SM_RS;
    float* cs  = sm + SM_CS;

    const int g  = blockIdx.y;
    const int ib = blockIdx.x;
    const float* __restrict__ Qh = g_q + (size_t)g * (SEQ * DPH);
    const float* __restrict__ Kh = g_k + (size_t)g * (SEQ * DPH);
    const float* __restrict__ Vh = g_v + (size_t)g * (SEQ * DPH);
    __nv_bfloat16* __restrict__ Eg = g_e + (size_t)g * SEQ * SEQ;

    const int t  = threadIdx.x;
    const int tx = t & 15;
    const int ty = t >> 4;
    const int r0 = ty * 4;
    const int c0 = tx * 4;

    // stage Q block k-major with swizzle
    #pragma unroll
    for (int it = 0; it < 8; it++) {
        int fid = t + it * 256;
        int row = fid >> 4;
        int d   = (fid & 15) * 4;
        float4 v = *reinterpret_cast<const float4*>(&Qh[(size_t)(ib * 128 + row) * DPH + d]);
        QsT[(d + 0) * 132 + (row ^ swz4(d + 0))] = v.x;
        QsT[(d + 1) * 132 + (row ^ swz4(d + 1))] = v.y;
        QsT[(d + 2) * 132 + (row ^ swz4(d + 2))] = v.z;
        QsT[(d + 3) * 132 + (row ^ swz4(d + 3))] = v.w;
    }
    if (t < 128) rs[t] = 0.0f;
    __syncthreads();

    // ------------- PASS 1: z = QK^T once; store bf16 E; row sums ----------
    for (int jb = 0; jb < 8; jb++) {
        #pragma unroll
        for (int it = 0; it < 8; it++) {
            int fid = t + it * 256;
            int row = fid >> 4;
            int d   = (fid & 15) * 4;
            float4 v = *reinterpret_cast<const float4*>(&Kh[(size_t)(jb * 128 + row) * DPH + d]);
            KsT[(d + 0) * 132 + (row ^ swz4(d + 0))] = v.x;
            KsT[(d + 1) * 132 + (row ^ swz4(d + 1))] = v.y;
            KsT[(d + 2) * 132 + (row ^ swz4(d + 2))] = v.z;
            KsT[(d + 3) * 132 + (row ^ swz4(d + 3))] = v.w;
        }
        __syncthreads();

        float z[8][8];
        #pragma unroll
        for (int i = 0; i < 8; i++)
            #pragma unroll
            for (int j = 0; j < 8; j++) z[i][j] = 0.0f;

        #pragma unroll 8
        for (int d = 0; d < 64; d++) {
            int sw = swz4(d);
            const float* qrow = &QsT[d * 132];
            const float* krow = &KsT[d * 132];
            float4 a0 = *reinterpret_cast<const float4*>(&qrow[r0 ^ sw]);
            float4 a1 = *reinterpret_cast<const float4*>(&qrow[(64 + r0) ^ sw]);
            float4 b0 = *reinterpret_cast<const float4*>(&krow[c0 ^ sw]);
            float4 b1 = *reinterpret_cast<const float4*>(&krow[(64 + c0) ^ sw]);
            float a[8] = {a0.x, a0.y, a0.z, a0.w, a1.x, a1.y, a1.z, a1.w};
            float b[8] = {b0.x, b0.y, b0.z, b0.w, b1.x, b1.y, b1.z, b1.w};
            #pragma unroll
            for (int i = 0; i < 8; i++)
                #pragma unroll
                for (int j = 0; j < 8; j++) z[i][j] += a[i] * b[j];
        }

        #pragma unroll
        for (int i = 0; i < 8; i++) {
            int row = (i < 4) ? (r0 + i) : (64 + r0 + i - 4);
            __nv_bfloat16 hb[8];
            float s = 0.0f;
            #pragma unroll
            for (int j = 0; j < 8; j++) {
                float ex = __expf(fmaxf(z[i][j] * ATT_SCALE, 0.0f));
                hb[j] = __float2bfloat16(ex);
                s += __bfloat162float(hb[j]);
            }
            __nv_bfloat16* erow = Eg + (size_t)(ib * 128 + row) * SEQ + jb * 128;
            union { __nv_bfloat162 h2[2]; uint2 u; } pa, pb;
            pa.h2[0] = __halves2bfloat162(hb[0], hb[1]);
            pa.h2[1] = __halves2bfloat162(hb[2], hb[3]);
            pb.h2[0] = __halves2bfloat162(hb[4], hb[5]);
            pb.h2[1] = __halves2bfloat162(hb[6], hb[7]);
            *reinterpret_cast<uint2*>(erow + c0) = pa.u;
            *reinterpret_cast<uint2*>(erow + 64 + c0) = pb.u;
            atomicAdd(&rs[row], s);
        }
        __syncthreads();
    }

    float rinv[8];
    #pragma unroll
    for (int i = 0; i < 8; i++) {
        int row = (i < 4) ? (r0 + i) : (64 + r0 + i - 4);
        rinv[i] = 1.0f / rs[row];
    }

    // ------------- PASS 2: read E, normalize, col sums, O = P @ V ----------
    float o[8][4];
    #pragma unroll
    for (int i = 0; i < 8; i++)
        #pragma unroll
        for (int c = 0; c < 4; c++) o[i][c] = 0.0f;

    for (int jb = 0; jb < 8; jb++) {
        #pragma unroll
        for (int it = 0; it < 8; it++) {
            int fid = t + it * 256;
            int row = fid >> 4;
            int d   = (fid & 15) * 4;
            float4 vv = *reinterpret_cast<const float4*>(&Vh[(size_t)(jb * 128 + row) * DPH + d]);
            *reinterpret_cast<float4*>(&Vs[row * 68 + d]) = vv;
        }
        if (t < 128) cs[t] = 0.0f;
        __syncthreads();

        // reload this thread's E tile
        float e[8][8];
        #pragma unroll
        for (int i = 0; i < 8; i++) {
            int row = (i < 4) ? (r0 + i) : (64 + r0 + i - 4);
            const __nv_bfloat16* erow = Eg + (size_t)(ib * 128 + row) * SEQ + jb * 128;
            uint2 ua = *reinterpret_cast<const uint2*>(erow + c0);
            uint2 ub = *reinterpret_cast<const uint2*>(erow + 64 + c0);
            float2 f;
            f = __bfloat1622float2(*reinterpret_cast<const __nv_bfloat162*>(&ua.x)); e[i][0] = f.x; e[i][1] = f.y;
            f = __bfloat1622float2(*reinterpret_cast<const __nv_bfloat162*>(&ua.y)); e[i][2] = f.x; e[i][3] = f.y;
            f = __bfloat1622float2(*reinterpret_cast<const __nv_bfloat162*>(&ub.x)); e[i][4] = f.x; e[i][5] = f.y;
            f = __bfloat1622float2(*reinterpret_cast<const __nv_bfloat162*>(&ub.y)); e[i][6] = f.x; e[i][7] = f.y;
        }

        #pragma unroll
        for (int j = 0; j < 8; j++) {
            int col = (j < 4) ? (c0 + j) : (64 + c0 + j - 4);
            int csw = swz4(col);
            float s = 0.0f;
            #pragma unroll
            for (int i = 0; i < 8; i++) {
                float p = e[i][j] * rinv[i];
                s += p;
                int row = (i < 4) ? (r0 + i) : (64 + r0 + i - 4);
                PsT[col * 132 + (row ^ csw)] = p;
            }
            atomicAdd(&cs[col], s);
        }
        __syncthreads();

        #pragma unroll 4
        for (int j = 0; j < 128; j++) {
            int jsw = swz4(j);
            const float* prow = &PsT[j * 132];
            float4 pa = *reinterpret_cast<const float4*>(&prow[r0 ^ jsw]);
            float4 pb = *reinterpret_cast<const float4*>(&prow[(64 + r0) ^ jsw]);
            float4 vv = *reinterpret_cast<const float4*>(&Vs[j * 68 + c0]);
            float p[8] = {pa.x, pa.y, pa.z, pa.w, pb.x, pb.y, pb.z, pb.w};
            #pragma unroll
            for (int i = 0; i < 8; i++) {
                o[i][0] += p[i] * vv.x;
                o[i][1] += p[i] * vv.y;
                o[i][2] += p[i] * vv.z;
                o[i][3] += p[i] * vv.w;
            }
        }

        if (t < 128) atomicAdd(&sums[g * 1024 + jb * 128 + t], cs[t]);
        __syncthreads();
    }

    float* __restrict__ Ch = g_ctx + (size_t)g * (SEQ * DPH);
    #pragma unroll
    for (int i = 0; i < 8; i++) {
        int row = ib * 128 + ((i < 4) ? (r0 + i) : (64 + r0 + i - 4));
        float4 ov; ov.x = o[i][0]; ov.y = o[i][1]; ov.z = o[i][2]; ov.w = o[i][3];
        *reinterpret_cast<float4*>(&Ch[(size_t)row * DPH + c0]) = ov;
    }
}

// ---------------------------------------------------------------------------
// Kernel 3: residual + LayerNorm
// ---------------------------------------------------------------------------
__global__ __launch_bounds__(256) void ln_kernel(
    const float* __restrict__ x,
    const float* __restrict__ gamma,
    const float* __restrict__ beta,
    float* __restrict__ out)
{
    const int row = blockIdx.x;
    const int t = threadIdx.x;
    const float* xr = x + (size_t)row * NTDIM;
    const float* cr = g_ctx + (size_t)row * NTDIM;

    float h[4];
    float s = 0.0f, sq = 0.0f;
    #pragma unroll
    for (int i = 0; i < 4; i++) {
        int idx = t + i * 256;
        h[i] = xr[idx] + cr[idx];
        s  += h[i];
        sq += h[i] * h[i];
    }
    #pragma unroll
    for (int off = 16; off; off >>= 1) {
        s  += __shfl_xor_sync(0xffffffffu, s,  off);
        sq += __shfl_xor_sync(0xffffffffu, sq, off);
    }
    __shared__ float rsum[8], rsq[8];
    int warp = t >> 5, lane = t & 31;
    if (lane == 0) { rsum[warp] = s; rsq[warp] = sq; }
    __syncthreads();
    float S = 0.0f, SQ = 0.0f;
    #pragma unroll
    for (int w = 0; w < 8; w++) { S += rsum[w]; SQ += rsq[w]; }
    float mean = S * (1.0f / NTDIM);
    float var  = SQ * (1.0f / NTDIM) - mean * mean;
    float inv  = rsqrtf(var + LNEPS);
    float* orow = out + (size_t)row * NTDIM;
    #pragma unroll
    for (int i = 0; i < 4; i++) {
        int idx = t + i * 256;
        orow[idx] = (h[i] - mean) * inv * gamma[idx] + beta[idx];
    }
}

// ---------------------------------------------------------------------------
extern "C" void kernel_launch(void* const* d_in, const int* in_sizes, int n_in,
                              void* d_out, int out_size)
{
    const float* x     = (const float*)d_in[0];
    const float* Wq    = (const float*)d_in[1];
    const float* bq    = (const float*)d_in[2];
    const float* Wk    = (const float*)d_in[3];
    const float* bk    = (const float*)d_in[4];
    const float* Wv    = (const float*)d_in[5];
    const float* bv    = (const float*)d_in[6];
    const float* gamma = (const float*)d_in[7];
    const float* beta  = (const float*)d_in[8];

    float* out  = (float*)d_out;
    float* sums = out + (size_t)M_ROWS * NTDIM;

    cudaFuncSetAttribute(attn_kernel,
                         cudaFuncAttributeMaxDynamicSharedMemorySize, ATT_SMEM_BYTES);
    cudaFuncSetAttribute(qkv_mma_kernel,
                         cudaFuncAttributeMaxDynamicSharedMemorySize, QKV_SMEM);

    zero_sums_kernel<<<256, 256>>>(sums);

    cvt_kernel<<<4096, 256>>>(x, 0);
    cvt_kernel<<<1024, 256>>>(Wq, 1);
    cvt_kernel<<<1024, 256>>>(Wk, 2);
    cvt_kernel<<<1024, 256>>>(Wv, 3);

    dim3 gq(8, 32, 3);
    qkv_mma_kernel<<<gq, 256, QKV_SMEM>>>(bq, bk, bv);

    dim3 ga(8, 64);
    attn_kernel<<<ga, 256, ATT_SMEM_BYTES>>>(sums);

    ln_kernel<<<M_ROWS, 256>>>(x, gamma, beta, out);
}

// round 5
// speedup vs baseline: 3.2670x; 2.0981x over previous
#include <cuda_runtime.h>
#include <cuda_bf16.h>
#include <cstdint>
#include <math.h>

// Problem constants
#define M_ROWS   4096      // B*S
#define NTDIM    1024
#define NGROUP   64        // B*heads
#define DPH      64
#define SEQ      1024
#define ATT_SCALE 0.03125f // 1024^-0.5
#define LNEPS    1e-5f

// Scratch (allocation-free rule: __device__ globals) — all bf16 hi/lo pairs
__device__ __nv_bfloat16 g_qh[M_ROWS * NTDIM];
__device__ __nv_bfloat16 g_ql[M_ROWS * NTDIM];
__device__ __nv_bfloat16 g_kh[M_ROWS * NTDIM];
__device__ __nv_bfloat16 g_kl[M_ROWS * NTDIM];
__device__ __nv_bfloat16 g_vh[M_ROWS * NTDIM];
__device__ __nv_bfloat16 g_vl[M_ROWS * NTDIM];
__device__ float g_ctx[M_ROWS * NTDIM];
__device__ __nv_bfloat16 g_xh[M_ROWS * NTDIM];
__device__ __nv_bfloat16 g_xl[M_ROWS * NTDIM];
__device__ __nv_bfloat16 g_wh[3 * NTDIM * NTDIM];
__device__ __nv_bfloat16 g_wl[3 * NTDIM * NTDIM];

// ===========================================================================
// PTX helpers: mma.sync (HMMA) + ldmatrix + cp.async
// ===========================================================================
__device__ __forceinline__ uint32_t smem_u32(const void* p) {
    uint32_t a;
    asm("{ .reg .u64 t; cvta.to.shared.u64 t, %1; cvt.u32.u64 %0, t; }" : "=r"(a) : "l"(p));
    return a;
}
__device__ __forceinline__ void ldsm_x4(uint32_t* r, uint32_t addr) {
    asm volatile("ldmatrix.sync.aligned.m8n8.x4.shared.b16 {%0,%1,%2,%3}, [%4];"
                 : "=r"(r[0]), "=r"(r[1]), "=r"(r[2]), "=r"(r[3]) : "r"(addr));
}
__device__ __forceinline__ void ldsm_x4_t(uint32_t* r, uint32_t addr) {
    asm volatile("ldmatrix.sync.aligned.m8n8.x4.trans.shared.b16 {%0,%1,%2,%3}, [%4];"
                 : "=r"(r[0]), "=r"(r[1]), "=r"(r[2]), "=r"(r[3]) : "r"(addr));
}
__device__ __forceinline__ void mma_bf16(float* d, const uint32_t* a,
                                         uint32_t b0, uint32_t b1) {
    asm volatile(
        "mma.sync.aligned.m16n8k16.row.col.f32.bf16.bf16.f32 "
        "{%0,%1,%2,%3}, {%4,%5,%6,%7}, {%8,%9}, {%0,%1,%2,%3};"
        : "+f"(d[0]), "+f"(d[1]), "+f"(d[2]), "+f"(d[3])
        : "r"(a[0]), "r"(a[1]), "r"(a[2]), "r"(a[3]), "r"(b0), "r"(b1));
}
__device__ __forceinline__ void cpa16(uint32_t dst, const void* src) {
    size_t gp;
    asm("cvta.to.global.u64 %0, %1;" : "=l"(gp) : "l"(src));
    asm volatile("cp.async.cg.shared.global [%0], [%1], 16;" :: "r"(dst), "l"(gp) : "memory");
}
__device__ __forceinline__ void cpa_commit() {
    asm volatile("cp.async.commit_group;" ::: "memory");
}
__device__ __forceinline__ void cpa_wait0() {
    asm volatile("cp.async.wait_group 0;" ::: "memory");
}
__device__ __forceinline__ uint32_t pack_bf2(__nv_bfloat16 a, __nv_bfloat16 b) {
    __nv_bfloat162 v = __halves2bfloat162(a, b);
    return *reinterpret_cast<uint32_t*>(&v);
}

// ---------------------------------------------------------------------------
// Kernel 0: zero the at_sum_sum region of d_out
// ---------------------------------------------------------------------------
__global__ void zero_sums_kernel(float* __restrict__ sums) {
    sums[blockIdx.x * 256 + threadIdx.x] = 0.0f;
}

// ---------------------------------------------------------------------------
// Kernel 0b: fp32 -> bf16 hi/lo split.  sel: 0 = x, 1..3 = Wq/Wk/Wv
// ---------------------------------------------------------------------------
__global__ __launch_bounds__(256) void cvt_kernel(const float* __restrict__ src, int sel) {
    __nv_bfloat16 *hi, *lo;
    if (sel == 0) { hi = g_xh; lo = g_xl; }
    else { hi = g_wh + (size_t)(sel - 1) * 1048576; lo = g_wl + (size_t)(sel - 1) * 1048576; }
    size_t i = ((size_t)blockIdx.x * 256 + threadIdx.x) * 4;
    float4 v = *reinterpret_cast<const float4*>(src + i);
    __nv_bfloat16 h0 = __float2bfloat16(v.x);
    __nv_bfloat16 h1 = __float2bfloat16(v.y);
    __nv_bfloat16 h2 = __float2bfloat16(v.z);
    __nv_bfloat16 h3 = __float2bfloat16(v.w);
    __nv_bfloat16 l0 = __float2bfloat16(v.x - __bfloat162float(h0));
    __nv_bfloat16 l1 = __float2bfloat16(v.y - __bfloat162float(h1));
    __nv_bfloat16 l2 = __float2bfloat16(v.z - __bfloat162float(h2));
    __nv_bfloat16 l3 = __float2bfloat16(v.w - __bfloat162float(h3));
    uint2 uh, ul;
    uh.x = pack_bf2(h0, h1); uh.y = pack_bf2(h2, h3);
    ul.x = pack_bf2(l0, l1); ul.y = pack_bf2(l2, l3);
    *reinterpret_cast<uint2*>(hi + i) = uh;
    *reinterpret_cast<uint2*>(lo + i) = ul;
}

// ---------------------------------------------------------------------------
// Kernel 1: QKV projection via mma.sync bf16 (split hi/lo x3, fp32 accum).
// C = X @ W^T + b, emitted as bf16 hi/lo pairs.  CTA tile 128x128, k-stage 64.
// ---------------------------------------------------------------------------
#define QST_AH 0
#define QST_AL 16384
#define QST_BH 32768
#define QST_BL 49152
#define QST_SZ 65536
#define QKV_SMEM (2 * QST_SZ)

__global__ __launch_bounds__(256) void qkv_mma_kernel(
    const float* __restrict__ bq, const float* __restrict__ bk, const float* __restrict__ bv)
{
    extern __shared__ char smc[];
    const uint32_t smb = smem_u32(smc);
    const int t = threadIdx.x;
    const int w = t >> 5;
    const int l = t & 31;
    const int z = blockIdx.z;
    const __nv_bfloat16* __restrict__ Wh = g_wh + (size_t)z * NTDIM * NTDIM;
    const __nv_bfloat16* __restrict__ Wl = g_wl + (size_t)z * NTDIM * NTDIM;
    const float* bias = (z == 0) ? bq : (z == 1) ? bk : bv;
    __nv_bfloat16* outh = (z == 0) ? g_qh : (z == 1) ? g_kh : g_vh;
    __nv_bfloat16* outl = (z == 0) ? g_ql : (z == 1) ? g_kl : g_vl;
    const int m0 = blockIdx.y * 128;
    const int n0 = blockIdx.x * 128;
    const int wr0 = (w >> 1) * 32;
    const int wn0 = (w & 1) * 64;

    const int sr[4] = { (t + 0) >> 3, (t + 256) >> 3, (t + 512) >> 3, (t + 768) >> 3 };
    const int sc = t & 7;

    float acc[2][8][4];
    #pragma unroll
    for (int a = 0; a < 2; a++)
        #pragma unroll
        for (int b = 0; b < 8; b++)
            #pragma unroll
            for (int c = 0; c < 4; c++) acc[a][b][c] = 0.0f;

    auto issue_stage = [&](int s, int buf) {
        const int k0 = s * 64;
        const uint32_t sb = smb + buf * QST_SZ;
        #pragma unroll
        for (int i = 0; i < 4; i++) {
            const int r = sr[i];
            const uint32_t doff = r * 128 + (((sc ^ (r & 7)) << 4));
            const size_t aoff = (size_t)(m0 + r) * NTDIM + k0 + sc * 8;
            const size_t boff = (size_t)(n0 + r) * NTDIM + k0 + sc * 8;
            cpa16(sb + QST_AH + doff, g_xh + aoff);
            cpa16(sb + QST_AL + doff, g_xl + aoff);
            cpa16(sb + QST_BH + doff, Wh + boff);
            cpa16(sb + QST_BL + doff, Wl + boff);
        }
        cpa_commit();
    };

    issue_stage(0, 0);

    for (int s = 0; s < 16; s++) {
        cpa_wait0();
        __syncthreads();
        if (s < 15) issue_stage(s + 1, (s + 1) & 1);
        const uint32_t bb = smb + (s & 1) * QST_SZ;

        #pragma unroll
        for (int kt = 0; kt < 4; kt++) {
            const int chunk = kt * 2 + (l >> 4);
            uint32_t ah[2][4], al[2][4];
            #pragma unroll
            for (int mf = 0; mf < 2; mf++) {
                const int r = wr0 + mf * 16 + (l & 15);
                const uint32_t ad = bb + r * 128 + (((chunk ^ (r & 7)) << 4));
                ldsm_x4(ah[mf], ad + QST_AH);
                ldsm_x4(al[mf], ad + QST_AL);
            }
            #pragma unroll
            for (int nq = 0; nq < 4; nq++) {
                const int rr = wn0 + nq * 16 + (l & 15);
                const uint32_t bd = bb + rr * 128 + (((chunk ^ (rr & 7)) << 4));
                uint32_t bh[4], bl[4];
                ldsm_x4(bh, bd + QST_BH);
                ldsm_x4(bl, bd + QST_BL);
                #pragma unroll
                for (int mf = 0; mf < 2; mf++) {
                    #pragma unroll
                    for (int nh = 0; nh < 2; nh++) {
                        float* d = acc[mf][nq * 2 + nh];
                        mma_bf16(d, ah[mf], bh[nh], bh[2 + nh]);
                        mma_bf16(d, ah[mf], bl[nh], bl[2 + nh]);
                        mma_bf16(d, al[mf], bh[nh], bh[2 + nh]);
                    }
                }
            }
        }
    }

    // epilogue: acc + bias -> bf16 hi/lo pairs
    const int lr = l >> 2;
    const int lc = (l & 3) * 2;
    #pragma unroll
    for (int mf = 0; mf < 2; mf++) {
        #pragma unroll
        for (int nf = 0; nf < 8; nf++) {
            const int col = n0 + wn0 + nf * 8 + lc;
            const int row = m0 + wr0 + mf * 16 + lr;
            const float* d = acc[mf][nf];
            float v0 = d[0] + bias[col];
            float v1 = d[1] + bias[col + 1];
            float v2 = d[2] + bias[col];
            float v3 = d[3] + bias[col + 1];
            __nv_bfloat16 h0 = __float2bfloat16(v0), h1 = __float2bfloat16(v1);
            __nv_bfloat16 h2 = __float2bfloat16(v2), h3 = __float2bfloat16(v3);
            __nv_bfloat16 e0 = __float2bfloat16(v0 - __bfloat162float(h0));
            __nv_bfloat16 e1 = __float2bfloat16(v1 - __bfloat162float(h1));
            __nv_bfloat16 e2 = __float2bfloat16(v2 - __bfloat162float(h2));
            __nv_bfloat16 e3 = __float2bfloat16(v3 - __bfloat162float(h3));
            *reinterpret_cast<uint32_t*>(outh + (size_t)row * NTDIM + col) = pack_bf2(h0, h1);
            *reinterpret_cast<uint32_t*>(outl + (size_t)row * NTDIM + col) = pack_bf2(e0, e1);
            *reinterpret_cast<uint32_t*>(outh + (size_t)(row + 8) * NTDIM + col) = pack_bf2(h2, h3);
            *reinterpret_cast<uint32_t*>(outl + (size_t)(row + 8) * NTDIM + col) = pack_bf2(e2, e3);
        }
    }
}

// ---------------------------------------------------------------------------
// Kernel 2: attention, fully tensorized.  CTA = 64 query rows x one head-group.
// E = exp(relu(z/32)) lives in SMEM (64x1024 bf16 = 128KB).
// Pass 1: z = QK^T (3-term bf16 MMA), E -> smem, rowsums.
// Pass 2: P = E*rinv (bf16), colsums, O = P @ V (2-term MMA, V via ldsm.trans).
// ---------------------------------------------------------------------------
#define A_ESM   0           // 64 x 2048B
#define A_QH    131072      // 64 x 128B
#define A_QL    139264
#define A_KV    147456      // 2 buffers x (H 16384 + L 16384)
#define A_RS    212992      // 64 floats
#define A_CS    213248      // 1024 floats
#define A_SMEM  217344

__global__ __launch_bounds__(256) void attn_mma_kernel(float* __restrict__ sums)
{
    extern __shared__ char smc[];
    const uint32_t smb = smem_u32(smc);
    float* rs = reinterpret_cast<float*>(smc + A_RS);
    float* cs = reinterpret_cast<float*>(smc + A_CS);

    const int ib = blockIdx.x;   // 0..15 (64-row block)
    const int g  = blockIdx.y;   // 0..63
    const int t  = threadIdx.x;
    const int w  = t >> 5;
    const int l  = t & 31;
    const int wm = w & 1;        // 2 row groups of 32
    const int wn = w >> 1;       // 4 col groups

    const __nv_bfloat16* __restrict__ qhp = g_qh + (size_t)g * 65536 + ib * 4096;
    const __nv_bfloat16* __restrict__ qlp = g_ql + (size_t)g * 65536 + ib * 4096;
    const __nv_bfloat16* __restrict__ khp = g_kh + (size_t)g * 65536;
    const __nv_bfloat16* __restrict__ klp = g_kl + (size_t)g * 65536;
    const __nv_bfloat16* __restrict__ vhp = g_vh + (size_t)g * 65536;
    const __nv_bfloat16* __restrict__ vlp = g_vl + (size_t)g * 65536;

    // init reductions
    if (t < 64) rs[t] = 0.0f;
    #pragma unroll
    for (int i = 0; i < 4; i++) cs[t + i * 256] = 0.0f;

    // stage Q (hi/lo) : 512 chunk-tasks x2
    #pragma unroll
    for (int i = 0; i < 2; i++) {
        int id = t + i * 256;         // 0..511
        int row = id >> 3, ch = id & 7;
        uint32_t doff = row * 128 + ((ch ^ (row & 7)) << 4);
        cpa16(smb + A_QH + doff, qhp + row * 64 + ch * 8);
        cpa16(smb + A_QL + doff, qlp + row * 64 + ch * 8);
    }
    // stage K block 0
    auto stage_kv = [&](const __nv_bfloat16* mh, const __nv_bfloat16* ml, int jb, int buf) {
        const uint32_t dst = smb + A_KV + buf * 32768;
        #pragma unroll
        for (int i = 0; i < 4; i++) {
            int id = t + i * 256;     // 0..1023
            int row = id >> 3, ch = id & 7;
            uint32_t doff = row * 128 + ((ch ^ (row & 7)) << 4);
            cpa16(dst + doff, mh + (size_t)(jb * 128 + row) * 64 + ch * 8);
            cpa16(dst + 16384 + doff, ml + (size_t)(jb * 128 + row) * 64 + ch * 8);
        }
        cpa_commit();
    };
    stage_kv(khp, klp, 0, 0);

    // ---------------- PASS 1 ----------------
    for (int jb = 0; jb < 8; jb++) {
        cpa_wait0();
        __syncthreads();
        if (jb < 7) stage_kv(khp, klp, jb + 1, (jb + 1) & 1);
        const uint32_t kb = smb + A_KV + (jb & 1) * 32768;

        float acc[2][4][4];
        #pragma unroll
        for (int a = 0; a < 2; a++)
            #pragma unroll
            for (int b = 0; b < 4; b++)
                #pragma unroll
                for (int c = 0; c < 4; c++) acc[a][b][c] = 0.0f;

        #pragma unroll
        for (int kc = 0; kc < 4; kc++) {
            const int chunk = kc * 2 + (l >> 4);
            uint32_t qh_[2][4], ql_[2][4];
            #pragma unroll
            for (int mf = 0; mf < 2; mf++) {
                const int r = wm * 32 + mf * 16 + (l & 15);
                const uint32_t ad = smb + r * 128 + ((chunk ^ (r & 7)) << 4);
                ldsm_x4(qh_[mf], ad + A_QH);
                ldsm_x4(ql_[mf], ad + A_QL);
            }
            #pragma unroll
            for (int nfp = 0; nfp < 2; nfp++) {
                const int rr = wn * 32 + nfp * 16 + (l & 15);
                const uint32_t bd = kb + rr * 128 + ((chunk ^ (rr & 7)) << 4);
                uint32_t bh[4], bl[4];
                ldsm_x4(bh, bd);
                ldsm_x4(bl, bd + 16384);
                #pragma unroll
                for (int mf = 0; mf < 2; mf++) {
                    #pragma unroll
                    for (int nh = 0; nh < 2; nh++) {
                        float* d = acc[mf][nfp * 2 + nh];
                        mma_bf16(d, qh_[mf], bh[nh], bh[2 + nh]);
                        mma_bf16(d, qh_[mf], bl[nh], bl[2 + nh]);
                        mma_bf16(d, ql_[mf], bh[nh], bh[2 + nh]);
                    }
                }
            }
        }

        // epilogue: E -> smem (bf16), rowsums of rounded E
        #pragma unroll
        for (int mf = 0; mf < 2; mf++) {
            const int rbase = wm * 32 + mf * 16 + (l >> 2);
            float s0 = 0.0f, s1 = 0.0f;
            #pragma unroll
            for (int nf = 0; nf < 4; nf++) {
                float* d = acc[mf][nf];
                const int col = jb * 128 + wn * 32 + nf * 8 + 2 * (l & 3);
                float e0 = __expf(fmaxf(d[0] * ATT_SCALE, 0.0f));
                float e1 = __expf(fmaxf(d[1] * ATT_SCALE, 0.0f));
                float e2 = __expf(fmaxf(d[2] * ATT_SCALE, 0.0f));
                float e3 = __expf(fmaxf(d[3] * ATT_SCALE, 0.0f));
                __nv_bfloat16 b0 = __float2bfloat16(e0), b1 = __float2bfloat16(e1);
                __nv_bfloat16 b2 = __float2bfloat16(e2), b3 = __float2bfloat16(e3);
                s0 += __bfloat162float(b0) + __bfloat162float(b1);
                s1 += __bfloat162float(b2) + __bfloat162float(b3);
                const int ch = col >> 3;
                const int off = (col & 7) * 2;
                *reinterpret_cast<uint32_t*>(smc + A_ESM + rbase * 2048 +
                    ((ch ^ (rbase & 7)) << 4) + off) = pack_bf2(b0, b1);
                *reinterpret_cast<uint32_t*>(smc + A_ESM + (rbase + 8) * 2048 +
                    ((ch ^ (rbase & 7)) << 4) + off) = pack_bf2(b2, b3);
            }
            s0 += __shfl_xor_sync(0xffffffffu, s0, 1);
            s0 += __shfl_xor_sync(0xffffffffu, s0, 2);
            s1 += __shfl_xor_sync(0xffffffffu, s1, 1);
            s1 += __shfl_xor_sync(0xffffffffu, s1, 2);
            if ((l & 3) == 0) {
                atomicAdd(&rs[rbase], s0);
                atomicAdd(&rs[rbase + 8], s1);
            }
        }
    }
    __syncthreads();   // rs complete; KV buffers free

    // per-thread 1/rowsum for pass-2 rows
    float rinvf[2][2];
    __nv_bfloat162 rb[2][2];
    #pragma unroll
    for (int mf = 0; mf < 2; mf++) {
        const int r = wm * 32 + mf * 16 + (l >> 2);
        rinvf[mf][0] = 1.0f / rs[r];
        rinvf[mf][1] = 1.0f / rs[r + 8];
        __nv_bfloat16 r0 = __float2bfloat16(rinvf[mf][0]);
        __nv_bfloat16 r1 = __float2bfloat16(rinvf[mf][1]);
        rb[mf][0] = __halves2bfloat162(r0, r0);
        rb[mf][1] = __halves2bfloat162(r1, r1);
    }

    // ---------------- PASS 2 ----------------
    stage_kv(vhp, vlp, 0, 0);

    float acc2[2][2][4];
    #pragma unroll
    for (int a = 0; a < 2; a++)
        #pragma unroll
        for (int b = 0; b < 2; b++)
            #pragma unroll
            for (int c = 0; c < 4; c++) acc2[a][b][c] = 0.0f;

    for (int jb = 0; jb < 8; jb++) {
        cpa_wait0();
        __syncthreads();
        if (jb < 7) stage_kv(vhp, vlp, jb + 1, (jb + 1) & 1);
        const uint32_t vb = smb + A_KV + (jb & 1) * 32768;

        #pragma unroll
        for (int kc2 = 0; kc2 < 8; kc2++) {
            // A = P fragments from smem E, scaled by rinv
            uint32_t pa[2][4];
            #pragma unroll
            for (int mf = 0; mf < 2; mf++) {
                const int r = wm * 32 + mf * 16 + (l & 15);
                const int ch = jb * 16 + kc2 * 2 + (l >> 4);
                uint32_t e4[4];
                ldsm_x4(e4, smb + A_ESM + r * 2048 + ((ch ^ (r & 7)) << 4));
                __nv_bfloat162 p0 = __hmul2(*reinterpret_cast<__nv_bfloat162*>(&e4[0]), rb[mf][0]);
                __nv_bfloat162 p1 = __hmul2(*reinterpret_cast<__nv_bfloat162*>(&e4[1]), rb[mf][1]);
                __nv_bfloat162 p2 = __hmul2(*reinterpret_cast<__nv_bfloat162*>(&e4[2]), rb[mf][0]);
                __nv_bfloat162 p3 = __hmul2(*reinterpret_cast<__nv_bfloat162*>(&e4[3]), rb[mf][1]);
                pa[mf][0] = *reinterpret_cast<uint32_t*>(&p0);
                pa[mf][1] = *reinterpret_cast<uint32_t*>(&p1);
                pa[mf][2] = *reinterpret_cast<uint32_t*>(&p2);
                pa[mf][3] = *reinterpret_cast<uint32_t*>(&p3);
            }
            // colsums (each warp owns 2 kc2 slots)
            if ((kc2 >> 1) == wn) {
                float c0 = 0, c1 = 0, c2 = 0, c3 = 0;
                #pragma unroll
                for (int mf = 0; mf < 2; mf++) {
                    float2 f0 = __bfloat1622float2(*reinterpret_cast<__nv_bfloat162*>(&pa[mf][0]));
                    float2 f1 = __bfloat1622float2(*reinterpret_cast<__nv_bfloat162*>(&pa[mf][1]));
                    float2 f2 = __bfloat1622float2(*reinterpret_cast<__nv_bfloat162*>(&pa[mf][2]));
                    float2 f3 = __bfloat1622float2(*reinterpret_cast<__nv_bfloat162*>(&pa[mf][3]));
                    c0 += f0.x + f1.x; c1 += f0.y + f1.y;
                    c2 += f2.x + f3.x; c3 += f2.y + f3.y;
                }
                #pragma unroll
                for (int m = 4; m < 32; m <<= 1) {
                    c0 += __shfl_xor_sync(0xffffffffu, c0, m);
                    c1 += __shfl_xor_sync(0xffffffffu, c1, m);
                    c2 += __shfl_xor_sync(0xffffffffu, c2, m);
                    c3 += __shfl_xor_sync(0xffffffffu, c3, m);
                }
                if (l < 4) {
                    const int cb = jb * 128 + kc2 * 16 + 2 * l;
                    atomicAdd(&cs[cb], c0);
                    atomicAdd(&cs[cb + 1], c1);
                    atomicAdd(&cs[cb + 8], c2);
                    atomicAdd(&cs[cb + 9], c3);
                }
            }
            // B = V via ldmatrix.trans
            const int krow = kc2 * 16 + (l & 7) + (((l >> 3) & 1) << 3);
            const int nch = wn * 2 + (l >> 4);
            const uint32_t vd = vb + krow * 128 + ((nch ^ (krow & 7)) << 4);
            uint32_t vh4[4], vl4[4];
            ldsm_x4_t(vh4, vd);
            ldsm_x4_t(vl4, vd + 16384);
            #pragma unroll
            for (int mf = 0; mf < 2; mf++) {
                #pragma unroll
                for (int nf = 0; nf < 2; nf++) {
                    float* d = acc2[mf][nf];
                    mma_bf16(d, pa[mf], vh4[2 * nf], vh4[2 * nf + 1]);
                    mma_bf16(d, pa[mf], vl4[2 * nf], vl4[2 * nf + 1]);
                }
            }
        }
    }

    // context epilogue
    float* __restrict__ Ch = g_ctx + (size_t)g * 65536 + ib * 4096;
    #pragma unroll
    for (int mf = 0; mf < 2; mf++) {
        #pragma unroll
        for (int nf = 0; nf < 2; nf++) {
            const int row = wm * 32 + mf * 16 + (l >> 2);
            const int col = wn * 16 + nf * 8 + 2 * (l & 3);
            const float* d = acc2[mf][nf];
            *reinterpret_cast<float2*>(Ch + (size_t)row * 64 + col) = make_float2(d[0], d[1]);
            *reinterpret_cast<float2*>(Ch + (size_t)(row + 8) * 64 + col) = make_float2(d[2], d[3]);
        }
    }

    // flush column sums
    __syncthreads();
    #pragma unroll
    for (int i = 0; i < 4; i++) {
        const int idx = t + i * 256;
        atomicAdd(&sums[g * 1024 + idx], cs[idx]);
    }
}

// ---------------------------------------------------------------------------
// Kernel 3: residual + LayerNorm
// ---------------------------------------------------------------------------
__global__ __launch_bounds__(256) void ln_kernel(
    const float* __restrict__ x,
    const float* __restrict__ gamma,
    const float* __restrict__ beta,
    float* __restrict__ out)
{
    const int row = blockIdx.x;
    const int t = threadIdx.x;
    const float* xr = x + (size_t)row * NTDIM;
    const float* cr = g_ctx + (size_t)row * NTDIM;

    float h[4];
    float s = 0.0f, sq = 0.0f;
    #pragma unroll
    for (int i = 0; i < 4; i++) {
        int idx = t + i * 256;
        h[i] = xr[idx] + cr[idx];
        s  += h[i];
        sq += h[i] * h[i];
    }
    #pragma unroll
    for (int off = 16; off; off >>= 1) {
        s  += __shfl_xor_sync(0xffffffffu, s,  off);
        sq += __shfl_xor_sync(0xffffffffu, sq, off);
    }
    __shared__ float rsum[8], rsq[8];
    int warp = t >> 5, lane = t & 31;
    if (lane == 0) { rsum[warp] = s; rsq[warp] = sq; }
    __syncthreads();
    float S = 0.0f, SQ = 0.0f;
    #pragma unroll
    for (int w = 0; w < 8; w++) { S += rsum[w]; SQ += rsq[w]; }
    float mean = S * (1.0f / NTDIM);
    float var  = SQ * (1.0f / NTDIM) - mean * mean;
    float inv  = rsqrtf(var + LNEPS);
    float* orow = out + (size_t)row * NTDIM;
    #pragma unroll
    for (int i = 0; i < 4; i++) {
        int idx = t + i * 256;
        orow[idx] = (h[i] - mean) * inv * gamma[idx] + beta[idx];
    }
}

// ---------------------------------------------------------------------------
extern "C" void kernel_launch(void* const* d_in, const int* in_sizes, int n_in,
                              void* d_out, int out_size)
{
    const float* x     = (const float*)d_in[0];
    const float* Wq    = (const float*)d_in[1];
    const float* bq    = (const float*)d_in[2];
    const float* Wk    = (const float*)d_in[3];
    const float* bk    = (const float*)d_in[4];
    const float* Wv    = (const float*)d_in[5];
    const float* bv    = (const float*)d_in[6];
    const float* gamma = (const float*)d_in[7];
    const float* beta  = (const float*)d_in[8];

    float* out  = (float*)d_out;
    float* sums = out + (size_t)M_ROWS * NTDIM;

    cudaFuncSetAttribute(qkv_mma_kernel,
                         cudaFuncAttributeMaxDynamicSharedMemorySize, QKV_SMEM);
    cudaFuncSetAttribute(attn_mma_kernel,
                         cudaFuncAttributeMaxDynamicSharedMemorySize, A_SMEM);

    zero_sums_kernel<<<256, 256>>>(sums);

    cvt_kernel<<<4096, 256>>>(x, 0);
    cvt_kernel<<<1024, 256>>>(Wq, 1);
    cvt_kernel<<<1024, 256>>>(Wk, 2);
    cvt_kernel<<<1024, 256>>>(Wv, 3);

    dim3 gq(8, 32, 3);
    qkv_mma_kernel<<<gq, 256, QKV_SMEM>>>(bq, bk, bv);

    dim3 ga(16, 64);
    attn_mma_kernel<<<ga, 256, A_SMEM>>>(sums);

    ln_kernel<<<M_ROWS, 256>>>(x, gamma, beta, out);
}

// round 6
// speedup vs baseline: 4.2090x; 1.2883x over previous
#include <cuda_runtime.h>
#include <cuda_bf16.h>
#include <cstdint>
#include <math.h>

// Problem constants
#define M_ROWS   4096      // B*S
#define NTDIM    1024
#define NGROUP   64        // B*heads
#define DPH      64
#define SEQ      1024
#define ATT_SCALE 0.03125f // 1024^-0.5
#define LNEPS    1e-5f

// Scratch (allocation-free rule: __device__ globals)
__device__ __nv_bfloat16 g_qh[M_ROWS * NTDIM];   // Q hi only
__device__ __nv_bfloat16 g_kh[M_ROWS * NTDIM];   // K hi
__device__ __nv_bfloat16 g_kl[M_ROWS * NTDIM];   // K lo
__device__ __nv_bfloat16 g_vh[M_ROWS * NTDIM];   // V hi only
__device__ float g_ctx[M_ROWS * NTDIM];
__device__ __nv_bfloat16 g_xh[M_ROWS * NTDIM];
__device__ __nv_bfloat16 g_xl[M_ROWS * NTDIM];
__device__ __nv_bfloat16 g_wh[3 * NTDIM * NTDIM]; // W hi only

// ===========================================================================
// PTX helpers: mma.sync (HMMA) + ldmatrix + cp.async
// ===========================================================================
__device__ __forceinline__ uint32_t smem_u32(const void* p) {
    uint32_t a;
    asm("{ .reg .u64 t; cvta.to.shared.u64 t, %1; cvt.u32.u64 %0, t; }" : "=r"(a) : "l"(p));
    return a;
}
__device__ __forceinline__ void ldsm_x4(uint32_t* r, uint32_t addr) {
    asm volatile("ldmatrix.sync.aligned.m8n8.x4.shared.b16 {%0,%1,%2,%3}, [%4];"
                 : "=r"(r[0]), "=r"(r[1]), "=r"(r[2]), "=r"(r[3]) : "r"(addr));
}
__device__ __forceinline__ void ldsm_x4_t(uint32_t* r, uint32_t addr) {
    asm volatile("ldmatrix.sync.aligned.m8n8.x4.trans.shared.b16 {%0,%1,%2,%3}, [%4];"
                 : "=r"(r[0]), "=r"(r[1]), "=r"(r[2]), "=r"(r[3]) : "r"(addr));
}
__device__ __forceinline__ void mma_bf16(float* d, const uint32_t* a,
                                         uint32_t b0, uint32_t b1) {
    asm volatile(
        "mma.sync.aligned.m16n8k16.row.col.f32.bf16.bf16.f32 "
        "{%0,%1,%2,%3}, {%4,%5,%6,%7}, {%8,%9}, {%0,%1,%2,%3};"
        : "+f"(d[0]), "+f"(d[1]), "+f"(d[2]), "+f"(d[3])
        : "r"(a[0]), "r"(a[1]), "r"(a[2]), "r"(a[3]), "r"(b0), "r"(b1));
}
__device__ __forceinline__ void cpa16(uint32_t dst, const void* src) {
    size_t gp;
    asm("cvta.to.global.u64 %0, %1;" : "=l"(gp) : "l"(src));
    asm volatile("cp.async.cg.shared.global [%0], [%1], 16;" :: "r"(dst), "l"(gp) : "memory");
}
__device__ __forceinline__ void cpa_commit() {
    asm volatile("cp.async.commit_group;" ::: "memory");
}
__device__ __forceinline__ void cpa_wait0() {
    asm volatile("cp.async.wait_group 0;" ::: "memory");
}
__device__ __forceinline__ uint32_t pack_bf2(__nv_bfloat16 a, __nv_bfloat16 b) {
    __nv_bfloat162 v = __halves2bfloat162(a, b);
    return *reinterpret_cast<uint32_t*>(&v);
}

// ---------------------------------------------------------------------------
// Kernel 0: zero the at_sum_sum region of d_out
// ---------------------------------------------------------------------------
__global__ void zero_sums_kernel(float* __restrict__ sums) {
    sums[blockIdx.x * 256 + threadIdx.x] = 0.0f;
}

// ---------------------------------------------------------------------------
// Kernel 0b: fp32 -> bf16.  sel 0 = x (hi/lo split), 1..3 = Wq/Wk/Wv (hi only)
// ---------------------------------------------------------------------------
__global__ __launch_bounds__(256) void cvt_kernel(const float* __restrict__ src, int sel) {
    size_t i = ((size_t)blockIdx.x * 256 + threadIdx.x) * 4;
    float4 v = *reinterpret_cast<const float4*>(src + i);
    __nv_bfloat16 h0 = __float2bfloat16(v.x);
    __nv_bfloat16 h1 = __float2bfloat16(v.y);
    __nv_bfloat16 h2 = __float2bfloat16(v.z);
    __nv_bfloat16 h3 = __float2bfloat16(v.w);
    uint2 uh;
    uh.x = pack_bf2(h0, h1); uh.y = pack_bf2(h2, h3);
    if (sel == 0) {
        __nv_bfloat16 l0 = __float2bfloat16(v.x - __bfloat162float(h0));
        __nv_bfloat16 l1 = __float2bfloat16(v.y - __bfloat162float(h1));
        __nv_bfloat16 l2 = __float2bfloat16(v.z - __bfloat162float(h2));
        __nv_bfloat16 l3 = __float2bfloat16(v.w - __bfloat162float(h3));
        uint2 ul;
        ul.x = pack_bf2(l0, l1); ul.y = pack_bf2(l2, l3);
        *reinterpret_cast<uint2*>(g_xh + i) = uh;
        *reinterpret_cast<uint2*>(g_xl + i) = ul;
    } else {
        *reinterpret_cast<uint2*>(g_wh + (size_t)(sel - 1) * 1048576 + i) = uh;
    }
}

// ---------------------------------------------------------------------------
// Kernel 1: QKV projection via mma.sync bf16, 2-term split (Xh+Xl) x Wh.
// C = X @ W^T + b -> bf16.  Q,V: hi only.  K: hi + lo residual.
// CTA tile 128x128, k-stage 64, double-buffered cp.async, SW-swizzled smem.
// ---------------------------------------------------------------------------
#define QST_AH 0
#define QST_AL 16384
#define QST_BH 32768
#define QST_SZ 49152
#define QKV_SMEM (2 * QST_SZ)

__global__ __launch_bounds__(256) void qkv_mma_kernel(
    const float* __restrict__ bq, const float* __restrict__ bk, const float* __restrict__ bv)
{
    extern __shared__ char smc[];
    const uint32_t smb = smem_u32(smc);
    const int t = threadIdx.x;
    const int w = t >> 5;
    const int l = t & 31;
    const int z = blockIdx.z;
    const __nv_bfloat16* __restrict__ Wh = g_wh + (size_t)z * NTDIM * NTDIM;
    const float* bias = (z == 0) ? bq : (z == 1) ? bk : bv;
    __nv_bfloat16* outh = (z == 0) ? g_qh : (z == 1) ? g_kh : g_vh;
    const bool store_lo = (z == 1);
    const int m0 = blockIdx.y * 128;
    const int n0 = blockIdx.x * 128;
    const int wr0 = (w >> 1) * 32;
    const int wn0 = (w & 1) * 64;

    const int sr[4] = { (t + 0) >> 3, (t + 256) >> 3, (t + 512) >> 3, (t + 768) >> 3 };
    const int sc = t & 7;

    float acc[2][8][4];
    #pragma unroll
    for (int a = 0; a < 2; a++)
        #pragma unroll
        for (int b = 0; b < 8; b++)
            #pragma unroll
            for (int c = 0; c < 4; c++) acc[a][b][c] = 0.0f;

    auto issue_stage = [&](int s, int buf) {
        const int k0 = s * 64;
        const uint32_t sb = smb + buf * QST_SZ;
        #pragma unroll
        for (int i = 0; i < 4; i++) {
            const int r = sr[i];
            const uint32_t doff = r * 128 + (((sc ^ (r & 7)) << 4));
            const size_t aoff = (size_t)(m0 + r) * NTDIM + k0 + sc * 8;
            const size_t boff = (size_t)(n0 + r) * NTDIM + k0 + sc * 8;
            cpa16(sb + QST_AH + doff, g_xh + aoff);
            cpa16(sb + QST_AL + doff, g_xl + aoff);
            cpa16(sb + QST_BH + doff, Wh + boff);
        }
        cpa_commit();
    };

    issue_stage(0, 0);

    for (int s = 0; s < 16; s++) {
        cpa_wait0();
        __syncthreads();
        if (s < 15) issue_stage(s + 1, (s + 1) & 1);
        const uint32_t bb = smb + (s & 1) * QST_SZ;

        #pragma unroll
        for (int kt = 0; kt < 4; kt++) {
            const int chunk = kt * 2 + (l >> 4);
            uint32_t ah[2][4], al[2][4];
            #pragma unroll
            for (int mf = 0; mf < 2; mf++) {
                const int r = wr0 + mf * 16 + (l & 15);
                const uint32_t ad = bb + r * 128 + (((chunk ^ (r & 7)) << 4));
                ldsm_x4(ah[mf], ad + QST_AH);
                ldsm_x4(al[mf], ad + QST_AL);
            }
            #pragma unroll
            for (int nq = 0; nq < 4; nq++) {
                const int rr = wn0 + nq * 16 + (l & 15);
                const uint32_t bd = bb + rr * 128 + (((chunk ^ (rr & 7)) << 4));
                uint32_t bh[4];
                ldsm_x4(bh, bd + QST_BH);
                #pragma unroll
                for (int mf = 0; mf < 2; mf++) {
                    #pragma unroll
                    for (int nh = 0; nh < 2; nh++) {
                        float* d = acc[mf][nq * 2 + nh];
                        mma_bf16(d, ah[mf], bh[nh], bh[2 + nh]);
                        mma_bf16(d, al[mf], bh[nh], bh[2 + nh]);
                    }
                }
            }
        }
    }

    // epilogue: acc + bias -> bf16 (hi; lo residual only for K)
    const int lr = l >> 2;
    const int lc = (l & 3) * 2;
    #pragma unroll
    for (int mf = 0; mf < 2; mf++) {
        #pragma unroll
        for (int nf = 0; nf < 8; nf++) {
            const int col = n0 + wn0 + nf * 8 + lc;
            const int row = m0 + wr0 + mf * 16 + lr;
            const float* d = acc[mf][nf];
            float v0 = d[0] + bias[col];
            float v1 = d[1] + bias[col + 1];
            float v2 = d[2] + bias[col];
            float v3 = d[3] + bias[col + 1];
            __nv_bfloat16 h0 = __float2bfloat16(v0), h1 = __float2bfloat16(v1);
            __nv_bfloat16 h2 = __float2bfloat16(v2), h3 = __float2bfloat16(v3);
            *reinterpret_cast<uint32_t*>(outh + (size_t)row * NTDIM + col) = pack_bf2(h0, h1);
            *reinterpret_cast<uint32_t*>(outh + (size_t)(row + 8) * NTDIM + col) = pack_bf2(h2, h3);
            if (store_lo) {
                __nv_bfloat16 e0 = __float2bfloat16(v0 - __bfloat162float(h0));
                __nv_bfloat16 e1 = __float2bfloat16(v1 - __bfloat162float(h1));
                __nv_bfloat16 e2 = __float2bfloat16(v2 - __bfloat162float(h2));
                __nv_bfloat16 e3 = __float2bfloat16(v3 - __bfloat162float(h3));
                *reinterpret_cast<uint32_t*>(g_kl + (size_t)row * NTDIM + col) = pack_bf2(e0, e1);
                *reinterpret_cast<uint32_t*>(g_kl + (size_t)(row + 8) * NTDIM + col) = pack_bf2(e2, e3);
            }
        }
    }
}

// ---------------------------------------------------------------------------
// Kernel 2: attention, fully tensorized.  CTA = 64 query rows x one head-group.
// E = exp(relu(z/32)) lives in SMEM (64x1024 bf16 = 128KB).
// Pass 1: z = Qh(Kh+Kl)^T (2-term MMA), E -> smem, rowsums.
// Pass 2: P = E*rinv (bf16), colsums, O = P @ Vh (1-term MMA, V via ldsm.trans).
// ---------------------------------------------------------------------------
#define A_ESM   0           // 64 x 2048B = 131072
#define A_QH    131072      // 64 x 128B = 8192
#define A_KV    139264      // 2 buffers x (hi 16384 + lo 16384) = 65536
#define A_RS    204800      // 64 floats
#define A_CS    205056      // 1024 floats
#define A_SMEM  209152

__global__ __launch_bounds__(256) void attn_mma_kernel(float* __restrict__ sums)
{
    extern __shared__ char smc[];
    const uint32_t smb = smem_u32(smc);
    float* rs = reinterpret_cast<float*>(smc + A_RS);
    float* cs = reinterpret_cast<float*>(smc + A_CS);

    const int ib = blockIdx.x;   // 0..15 (64-row block)
    const int g  = blockIdx.y;   // 0..63
    const int t  = threadIdx.x;
    const int w  = t >> 5;
    const int l  = t & 31;
    const int wm = w & 1;        // 2 row groups of 32
    const int wn = w >> 1;       // 4 col groups

    const __nv_bfloat16* __restrict__ qhp = g_qh + (size_t)g * 65536 + ib * 4096;
    const __nv_bfloat16* __restrict__ khp = g_kh + (size_t)g * 65536;
    const __nv_bfloat16* __restrict__ klp = g_kl + (size_t)g * 65536;
    const __nv_bfloat16* __restrict__ vhp = g_vh + (size_t)g * 65536;

    // init reductions
    if (t < 64) rs[t] = 0.0f;
    #pragma unroll
    for (int i = 0; i < 4; i++) cs[t + i * 256] = 0.0f;

    // stage Q hi: 512 chunk-tasks
    #pragma unroll
    for (int i = 0; i < 2; i++) {
        int id = t + i * 256;         // 0..511
        int row = id >> 3, ch = id & 7;
        uint32_t doff = row * 128 + ((ch ^ (row & 7)) << 4);
        cpa16(smb + A_QH + doff, qhp + row * 64 + ch * 8);
    }
    // stage K/V block: hi always, lo only for K
    auto stage_kv = [&](const __nv_bfloat16* mh, const __nv_bfloat16* ml, int jb,
                        int buf, bool lo) {
        const uint32_t dst = smb + A_KV + buf * 32768;
        #pragma unroll
        for (int i = 0; i < 4; i++) {
            int id = t + i * 256;     // 0..1023
            int row = id >> 3, ch = id & 7;
            uint32_t doff = row * 128 + ((ch ^ (row & 7)) << 4);
            cpa16(dst + doff, mh + (size_t)(jb * 128 + row) * 64 + ch * 8);
            if (lo) cpa16(dst + 16384 + doff, ml + (size_t)(jb * 128 + row) * 64 + ch * 8);
        }
        cpa_commit();
    };
    stage_kv(khp, klp, 0, 0, true);

    // ---------------- PASS 1 ----------------
    for (int jb = 0; jb < 8; jb++) {
        cpa_wait0();
        __syncthreads();
        if (jb < 7) stage_kv(khp, klp, jb + 1, (jb + 1) & 1, true);
        const uint32_t kb = smb + A_KV + (jb & 1) * 32768;

        float acc[2][4][4];
        #pragma unroll
        for (int a = 0; a < 2; a++)
            #pragma unroll
            for (int b = 0; b < 4; b++)
                #pragma unroll
                for (int c = 0; c < 4; c++) acc[a][b][c] = 0.0f;

        #pragma unroll
        for (int kc = 0; kc < 4; kc++) {
            const int chunk = kc * 2 + (l >> 4);
            uint32_t qh_[2][4];
            #pragma unroll
            for (int mf = 0; mf < 2; mf++) {
                const int r = wm * 32 + mf * 16 + (l & 15);
                const uint32_t ad = smb + r * 128 + ((chunk ^ (r & 7)) << 4);
                ldsm_x4(qh_[mf], ad + A_QH);
            }
            #pragma unroll
            for (int nfp = 0; nfp < 2; nfp++) {
                const int rr = wn * 32 + nfp * 16 + (l & 15);
                const uint32_t bd = kb + rr * 128 + ((chunk ^ (rr & 7)) << 4);
                uint32_t bh[4], bl[4];
                ldsm_x4(bh, bd);
                ldsm_x4(bl, bd + 16384);
                #pragma unroll
                for (int mf = 0; mf < 2; mf++) {
                    #pragma unroll
                    for (int nh = 0; nh < 2; nh++) {
                        float* d = acc[mf][nfp * 2 + nh];
                        mma_bf16(d, qh_[mf], bh[nh], bh[2 + nh]);
                        mma_bf16(d, qh_[mf], bl[nh], bl[2 + nh]);
                    }
                }
            }
        }

        // epilogue: E -> smem (bf16), rowsums of rounded E
        #pragma unroll
        for (int mf = 0; mf < 2; mf++) {
            const int rbase = wm * 32 + mf * 16 + (l >> 2);
            float s0 = 0.0f, s1 = 0.0f;
            #pragma unroll
            for (int nf = 0; nf < 4; nf++) {
                float* d = acc[mf][nf];
                const int col = jb * 128 + wn * 32 + nf * 8 + 2 * (l & 3);
                float e0 = __expf(fmaxf(d[0] * ATT_SCALE, 0.0f));
                float e1 = __expf(fmaxf(d[1] * ATT_SCALE, 0.0f));
                float e2 = __expf(fmaxf(d[2] * ATT_SCALE, 0.0f));
                float e3 = __expf(fmaxf(d[3] * ATT_SCALE, 0.0f));
                __nv_bfloat16 b0 = __float2bfloat16(e0), b1 = __float2bfloat16(e1);
                __nv_bfloat16 b2 = __float2bfloat16(e2), b3 = __float2bfloat16(e3);
                s0 += __bfloat162float(b0) + __bfloat162float(b1);
                s1 += __bfloat162float(b2) + __bfloat162float(b3);
                const int ch = col >> 3;
                const int off = (col & 7) * 2;
                *reinterpret_cast<uint32_t*>(smc + A_ESM + rbase * 2048 +
                    ((ch ^ (rbase & 7)) << 4) + off) = pack_bf2(b0, b1);
                *reinterpret_cast<uint32_t*>(smc + A_ESM + (rbase + 8) * 2048 +
                    ((ch ^ (rbase & 7)) << 4) + off) = pack_bf2(b2, b3);
            }
            s0 += __shfl_xor_sync(0xffffffffu, s0, 1);
            s0 += __shfl_xor_sync(0xffffffffu, s0, 2);
            s1 += __shfl_xor_sync(0xffffffffu, s1, 1);
            s1 += __shfl_xor_sync(0xffffffffu, s1, 2);
            if ((l & 3) == 0) {
                atomicAdd(&rs[rbase], s0);
                atomicAdd(&rs[rbase + 8], s1);
            }
        }
    }
    __syncthreads();   // rs complete; KV buffers free

    // per-thread 1/rowsum for pass-2 rows
    __nv_bfloat162 rb[2][2];
    #pragma unroll
    for (int mf = 0; mf < 2; mf++) {
        const int r = wm * 32 + mf * 16 + (l >> 2);
        __nv_bfloat16 r0 = __float2bfloat16(1.0f / rs[r]);
        __nv_bfloat16 r1 = __float2bfloat16(1.0f / rs[r + 8]);
        rb[mf][0] = __halves2bfloat162(r0, r0);
        rb[mf][1] = __halves2bfloat162(r1, r1);
    }

    // ---------------- PASS 2 ----------------
    stage_kv(vhp, vhp, 0, 0, false);

    float acc2[2][2][4];
    #pragma unroll
    for (int a = 0; a < 2; a++)
        #pragma unroll
        for (int b = 0; b < 2; b++)
            #pragma unroll
            for (int c = 0; c < 4; c++) acc2[a][b][c] = 0.0f;

    for (int jb = 0; jb < 8; jb++) {
        cpa_wait0();
        __syncthreads();
        if (jb < 7) stage_kv(vhp, vhp, jb + 1, (jb + 1) & 1, false);
        const uint32_t vb = smb + A_KV + (jb & 1) * 32768;

        #pragma unroll
        for (int kc2 = 0; kc2 < 8; kc2++) {
            // A = P fragments from smem E, scaled by rinv
            uint32_t pa[2][4];
            #pragma unroll
            for (int mf = 0; mf < 2; mf++) {
                const int r = wm * 32 + mf * 16 + (l & 15);
                const int ch = jb * 16 + kc2 * 2 + (l >> 4);
                uint32_t e4[4];
                ldsm_x4(e4, smb + A_ESM + r * 2048 + ((ch ^ (r & 7)) << 4));
                __nv_bfloat162 p0 = __hmul2(*reinterpret_cast<__nv_bfloat162*>(&e4[0]), rb[mf][0]);
                __nv_bfloat162 p1 = __hmul2(*reinterpret_cast<__nv_bfloat162*>(&e4[1]), rb[mf][1]);
                __nv_bfloat162 p2 = __hmul2(*reinterpret_cast<__nv_bfloat162*>(&e4[2]), rb[mf][0]);
                __nv_bfloat162 p3 = __hmul2(*reinterpret_cast<__nv_bfloat162*>(&e4[3]), rb[mf][1]);
                pa[mf][0] = *reinterpret_cast<uint32_t*>(&p0);
                pa[mf][1] = *reinterpret_cast<uint32_t*>(&p1);
                pa[mf][2] = *reinterpret_cast<uint32_t*>(&p2);
                pa[mf][3] = *reinterpret_cast<uint32_t*>(&p3);
            }
            // colsums (each warp owns 2 kc2 slots)
            if ((kc2 >> 1) == wn) {
                float c0 = 0, c1 = 0, c2 = 0, c3 = 0;
                #pragma unroll
                for (int mf = 0; mf < 2; mf++) {
                    float2 f0 = __bfloat1622float2(*reinterpret_cast<__nv_bfloat162*>(&pa[mf][0]));
                    float2 f1 = __bfloat1622float2(*reinterpret_cast<__nv_bfloat162*>(&pa[mf][1]));
                    float2 f2 = __bfloat1622float2(*reinterpret_cast<__nv_bfloat162*>(&pa[mf][2]));
                    float2 f3 = __bfloat1622float2(*reinterpret_cast<__nv_bfloat162*>(&pa[mf][3]));
                    c0 += f0.x + f1.x; c1 += f0.y + f1.y;
                    c2 += f2.x + f3.x; c3 += f2.y + f3.y;
                }
                #pragma unroll
                for (int m = 4; m < 32; m <<= 1) {
                    c0 += __shfl_xor_sync(0xffffffffu, c0, m);
                    c1 += __shfl_xor_sync(0xffffffffu, c1, m);
                    c2 += __shfl_xor_sync(0xffffffffu, c2, m);
                    c3 += __shfl_xor_sync(0xffffffffu, c3, m);
                }
                if (l < 4) {
                    const int cb = jb * 128 + kc2 * 16 + 2 * l;
                    atomicAdd(&cs[cb], c0);
                    atomicAdd(&cs[cb + 1], c1);
                    atomicAdd(&cs[cb + 8], c2);
                    atomicAdd(&cs[cb + 9], c3);
                }
            }
            // B = V via ldmatrix.trans
            const int krow = kc2 * 16 + (l & 7) + (((l >> 3) & 1) << 3);
            const int nch = wn * 2 + (l >> 4);
            const uint32_t vd = vb + krow * 128 + ((nch ^ (krow & 7)) << 4);
            uint32_t vh4[4];
            ldsm_x4_t(vh4, vd);
            #pragma unroll
            for (int mf = 0; mf < 2; mf++) {
                #pragma unroll
                for (int nf = 0; nf < 2; nf++) {
                    mma_bf16(acc2[mf][nf], pa[mf], vh4[2 * nf], vh4[2 * nf + 1]);
                }
            }
        }
    }

    // context epilogue
    float* __restrict__ Ch = g_ctx + (size_t)g * 65536 + ib * 4096;
    #pragma unroll
    for (int mf = 0; mf < 2; mf++) {
        #pragma unroll
        for (int nf = 0; nf < 2; nf++) {
            const int row = wm * 32 + mf * 16 + (l >> 2);
            const int col = wn * 16 + nf * 8 + 2 * (l & 3);
            const float* d = acc2[mf][nf];
            *reinterpret_cast<float2*>(Ch + (size_t)row * 64 + col) = make_float2(d[0], d[1]);
            *reinterpret_cast<float2*>(Ch + (size_t)(row + 8) * 64 + col) = make_float2(d[2], d[3]);
        }
    }

    // flush column sums
    __syncthreads();
    #pragma unroll
    for (int i = 0; i < 4; i++) {
        const int idx = t + i * 256;
        atomicAdd(&sums[g * 1024 + idx], cs[idx]);
    }
}

// ---------------------------------------------------------------------------
// Kernel 3: residual + LayerNorm
// ---------------------------------------------------------------------------
__global__ __launch_bounds__(256) void ln_kernel(
    const float* __restrict__ x,
    const float* __restrict__ gamma,
    const float* __restrict__ beta,
    float* __restrict__ out)
{
    const int row = blockIdx.x;
    const int t = threadIdx.x;
    const float* xr = x + (size_t)row * NTDIM;
    const float* cr = g_ctx + (size_t)row * NTDIM;

    float h[4];
    float s = 0.0f, sq = 0.0f;
    #pragma unroll
    for (int i = 0; i < 4; i++) {
        int idx = t + i * 256;
        h[i] = xr[idx] + cr[idx];
        s  += h[i];
        sq += h[i] * h[i];
    }
    #pragma unroll
    for (int off = 16; off; off >>= 1) {
        s  += __shfl_xor_sync(0xffffffffu, s,  off);
        sq += __shfl_xor_sync(0xffffffffu, sq, off);
    }
    __shared__ float rsum[8], rsq[8];
    int warp = t >> 5, lane = t & 31;
    if (lane == 0) { rsum[warp] = s; rsq[warp] = sq; }
    __syncthreads();
    float S = 0.0f, SQ = 0.0f;
    #pragma unroll
    for (int w = 0; w < 8; w++) { S += rsum[w]; SQ += rsq[w]; }
    float mean = S * (1.0f / NTDIM);
    float var  = SQ * (1.0f / NTDIM) - mean * mean;
    float inv  = rsqrtf(var + LNEPS);
    float* orow = out + (size_t)row * NTDIM;
    #pragma unroll
    for (int i = 0; i < 4; i++) {
        int idx = t + i * 256;
        orow[idx] = (h[i] - mean) * inv * gamma[idx] + beta[idx];
    }
}

// ---------------------------------------------------------------------------
extern "C" void kernel_launch(void* const* d_in, const int* in_sizes, int n_in,
                              void* d_out, int out_size)
{
    const float* x     = (const float*)d_in[0];
    const float* Wq    = (const float*)d_in[1];
    const float* bq    = (const float*)d_in[2];
    const float* Wk    = (const float*)d_in[3];
    const float* bk    = (const float*)d_in[4];
    const float* Wv    = (const float*)d_in[5];
    const float* bv    = (const float*)d_in[6];
    const float* gamma = (const float*)d_in[7];
    const float* beta  = (const float*)d_in[8];

    float* out  = (float*)d_out;
    float* sums = out + (size_t)M_ROWS * NTDIM;

    cudaFuncSetAttribute(qkv_mma_kernel,
                         cudaFuncAttributeMaxDynamicSharedMemorySize, QKV_SMEM);
    cudaFuncSetAttribute(attn_mma_kernel,
                         cudaFuncAttributeMaxDynamicSharedMemorySize, A_SMEM);

    zero_sums_kernel<<<256, 256>>>(sums);

    cvt_kernel<<<4096, 256>>>(x, 0);
    cvt_kernel<<<1024, 256>>>(Wq, 1);
    cvt_kernel<<<1024, 256>>>(Wk, 2);
    cvt_kernel<<<1024, 256>>>(Wv, 3);

    dim3 gq(8, 32, 3);
    qkv_mma_kernel<<<gq, 256, QKV_SMEM>>>(bq, bk, bv);

    dim3 ga(16, 64);
    attn_mma_kernel<<<ga, 256, A_SMEM>>>(sums);

    ln_kernel<<<M_ROWS, 256>>>(x, gamma, beta, out);
}

// round 7
// speedup vs baseline: 7.0481x; 1.6745x over previous
#include <cuda_runtime.h>
#include <cuda_bf16.h>
#include <cstdint>
#include <math.h>

// Problem constants
#define M_ROWS   4096      // B*S
#define NTDIM    1024
#define NGROUP   64        // B*heads
#define DPH      64
#define SEQ      1024
#define ATT_SCALE 0.03125f // 1024^-0.5
#define LNEPS    1e-5f

// Scratch (allocation-free rule: __device__ globals)
__device__ __nv_bfloat16 g_qh[M_ROWS * NTDIM];
__device__ __nv_bfloat16 g_kh[M_ROWS * NTDIM];
__device__ __nv_bfloat16 g_vh[M_ROWS * NTDIM];
__device__ float g_ctx[M_ROWS * NTDIM];
__device__ __nv_bfloat16 g_xh[M_ROWS * NTDIM];
__device__ __nv_bfloat16 g_wh[3 * NTDIM * NTDIM];

// ===========================================================================
// PTX helpers: mma.sync (HMMA) + ldmatrix + cp.async
// ===========================================================================
__device__ __forceinline__ uint32_t smem_u32(const void* p) {
    uint32_t a;
    asm("{ .reg .u64 t; cvta.to.shared.u64 t, %1; cvt.u32.u64 %0, t; }" : "=r"(a) : "l"(p));
    return a;
}
__device__ __forceinline__ void ldsm_x4(uint32_t* r, uint32_t addr) {
    asm volatile("ldmatrix.sync.aligned.m8n8.x4.shared.b16 {%0,%1,%2,%3}, [%4];"
                 : "=r"(r[0]), "=r"(r[1]), "=r"(r[2]), "=r"(r[3]) : "r"(addr));
}
__device__ __forceinline__ void ldsm_x4_t(uint32_t* r, uint32_t addr) {
    asm volatile("ldmatrix.sync.aligned.m8n8.x4.trans.shared.b16 {%0,%1,%2,%3}, [%4];"
                 : "=r"(r[0]), "=r"(r[1]), "=r"(r[2]), "=r"(r[3]) : "r"(addr));
}
__device__ __forceinline__ void mma_bf16(float* d, const uint32_t* a,
                                         uint32_t b0, uint32_t b1) {
    asm volatile(
        "mma.sync.aligned.m16n8k16.row.col.f32.bf16.bf16.f32 "
        "{%0,%1,%2,%3}, {%4,%5,%6,%7}, {%8,%9}, {%0,%1,%2,%3};"
        : "+f"(d[0]), "+f"(d[1]), "+f"(d[2]), "+f"(d[3])
        : "r"(a[0]), "r"(a[1]), "r"(a[2]), "r"(a[3]), "r"(b0), "r"(b1));
}
__device__ __forceinline__ void cpa16(uint32_t dst, const void* src) {
    size_t gp;
    asm("cvta.to.global.u64 %0, %1;" : "=l"(gp) : "l"(src));
    asm volatile("cp.async.cg.shared.global [%0], [%1], 16;" :: "r"(dst), "l"(gp) : "memory");
}
__device__ __forceinline__ void cpa_commit() {
    asm volatile("cp.async.commit_group;" ::: "memory");
}
__device__ __forceinline__ void cpa_wait0() {
    asm volatile("cp.async.wait_group 0;" ::: "memory");
}
__device__ __forceinline__ uint32_t pack_bf2(__nv_bfloat16 a, __nv_bfloat16 b) {
    __nv_bfloat162 v = __halves2bfloat162(a, b);
    return *reinterpret_cast<uint32_t*>(&v);
}

// ---------------------------------------------------------------------------
// Kernel 0: zero the at_sum_sum region of d_out
// ---------------------------------------------------------------------------
__global__ void zero_sums_kernel(float* __restrict__ sums) {
    sums[blockIdx.x * 256 + threadIdx.x] = 0.0f;
}

// ---------------------------------------------------------------------------
// Kernel 0b: fp32 -> bf16 (hi only).  sel 0 = x, 1..3 = Wq/Wk/Wv
// ---------------------------------------------------------------------------
__global__ __launch_bounds__(256) void cvt_kernel(const float* __restrict__ src, int sel) {
    size_t i = ((size_t)blockIdx.x * 256 + threadIdx.x) * 4;
    float4 v = *reinterpret_cast<const float4*>(src + i);
    uint2 uh;
    uh.x = pack_bf2(__float2bfloat16(v.x), __float2bfloat16(v.y));
    uh.y = pack_bf2(__float2bfloat16(v.z), __float2bfloat16(v.w));
    __nv_bfloat16* dst = (sel == 0) ? g_xh : g_wh + (size_t)(sel - 1) * 1048576;
    *reinterpret_cast<uint2*>(dst + i) = uh;
}

// ---------------------------------------------------------------------------
// Kernel 1: QKV projection via mma.sync bf16, 1-term (Xh x Wh), fp32 accum.
// C = X @ W^T + b -> bf16 hi.  CTA tile 128x128, k-stage 64, double-buffered.
// ---------------------------------------------------------------------------
#define QST_AH 0
#define QST_BH 16384
#define QST_SZ 32768
#define QKV_SMEM (2 * QST_SZ)

__global__ __launch_bounds__(256) void qkv_mma_kernel(
    const float* __restrict__ bq, const float* __restrict__ bk, const float* __restrict__ bv)
{
    extern __shared__ char smc[];
    const uint32_t smb = smem_u32(smc);
    const int t = threadIdx.x;
    const int w = t >> 5;
    const int l = t & 31;
    const int z = blockIdx.z;
    const __nv_bfloat16* __restrict__ Wh = g_wh + (size_t)z * NTDIM * NTDIM;
    const float* bias = (z == 0) ? bq : (z == 1) ? bk : bv;
    __nv_bfloat16* outh = (z == 0) ? g_qh : (z == 1) ? g_kh : g_vh;
    const int m0 = blockIdx.y * 128;
    const int n0 = blockIdx.x * 128;
    const int wr0 = (w >> 1) * 32;
    const int wn0 = (w & 1) * 64;

    const int sr[4] = { (t + 0) >> 3, (t + 256) >> 3, (t + 512) >> 3, (t + 768) >> 3 };
    const int sc = t & 7;

    float acc[2][8][4];
    #pragma unroll
    for (int a = 0; a < 2; a++)
        #pragma unroll
        for (int b = 0; b < 8; b++)
            #pragma unroll
            for (int c = 0; c < 4; c++) acc[a][b][c] = 0.0f;

    auto issue_stage = [&](int s, int buf) {
        const int k0 = s * 64;
        const uint32_t sb = smb + buf * QST_SZ;
        #pragma unroll
        for (int i = 0; i < 4; i++) {
            const int r = sr[i];
            const uint32_t doff = r * 128 + (((sc ^ (r & 7)) << 4));
            cpa16(sb + QST_AH + doff, g_xh + (size_t)(m0 + r) * NTDIM + k0 + sc * 8);
            cpa16(sb + QST_BH + doff, Wh + (size_t)(n0 + r) * NTDIM + k0 + sc * 8);
        }
        cpa_commit();
    };

    issue_stage(0, 0);

    for (int s = 0; s < 16; s++) {
        cpa_wait0();
        __syncthreads();
        if (s < 15) issue_stage(s + 1, (s + 1) & 1);
        const uint32_t bb = smb + (s & 1) * QST_SZ;

        #pragma unroll
        for (int kt = 0; kt < 4; kt++) {
            const int chunk = kt * 2 + (l >> 4);
            uint32_t ah[2][4];
            #pragma unroll
            for (int mf = 0; mf < 2; mf++) {
                const int r = wr0 + mf * 16 + (l & 15);
                ldsm_x4(ah[mf], bb + QST_AH + r * 128 + (((chunk ^ (r & 7)) << 4)));
            }
            #pragma unroll
            for (int nq = 0; nq < 4; nq++) {
                const int rr = wn0 + nq * 16 + (l & 15);
                uint32_t bh[4];
                ldsm_x4(bh, bb + QST_BH + rr * 128 + (((chunk ^ (rr & 7)) << 4)));
                #pragma unroll
                for (int mf = 0; mf < 2; mf++) {
                    #pragma unroll
                    for (int nh = 0; nh < 2; nh++)
                        mma_bf16(acc[mf][nq * 2 + nh], ah[mf], bh[nh], bh[2 + nh]);
                }
            }
        }
    }

    // epilogue: acc + bias -> bf16
    const int lr = l >> 2;
    const int lc = (l & 3) * 2;
    #pragma unroll
    for (int mf = 0; mf < 2; mf++) {
        #pragma unroll
        for (int nf = 0; nf < 8; nf++) {
            const int col = n0 + wn0 + nf * 8 + lc;
            const int row = m0 + wr0 + mf * 16 + lr;
            const float* d = acc[mf][nf];
            *reinterpret_cast<uint32_t*>(outh + (size_t)row * NTDIM + col) =
                pack_bf2(__float2bfloat16(d[0] + bias[col]),
                         __float2bfloat16(d[1] + bias[col + 1]));
            *reinterpret_cast<uint32_t*>(outh + (size_t)(row + 8) * NTDIM + col) =
                pack_bf2(__float2bfloat16(d[2] + bias[col]),
                         __float2bfloat16(d[3] + bias[col + 1]));
        }
    }
}

// ---------------------------------------------------------------------------
// Kernel 2: attention, single fused pass.  CTA = 64 query rows x head-group.
// Per K/V block: z = Qh Kh^T (MMA), E = exp(relu(z/32)) -> smem + register
// A-fragments, EV += E @ Vh (MMA, C-frag -> A-frag recycling), rowsums.
// Epilogue: ctx = diag(1/rs) * EV (4-warp smem reduce); colsums = E^T (1/rs).
// ---------------------------------------------------------------------------
#define A_ESM   0           // 64 x 2048B = 131072
#define A_QH    131072      // 8192
#define A_KV    139264      // 2 x (K 16384 + V 16384) = 65536 (loop only)
#define A_RED   139264      // 4 x 17408 = 69632 (epilogue, reuses KV)
#define A_RS    208896      // 64 floats
#define A_SMEM  209152

__global__ __launch_bounds__(256) void attn_mma_kernel(float* __restrict__ sums)
{
    extern __shared__ char smc[];
    const uint32_t smb = smem_u32(smc);
    float* rs = reinterpret_cast<float*>(smc + A_RS);

    const int ib = blockIdx.x;   // 0..15 (64-row block)
    const int g  = blockIdx.y;   // 0..63
    const int t  = threadIdx.x;
    const int w  = t >> 5;
    const int l  = t & 31;
    const int wm = w & 1;        // 2 row groups of 32
    const int wn = w >> 1;       // 4 col (k-slice) groups of 32

    const __nv_bfloat16* __restrict__ qhp = g_qh + (size_t)g * 65536 + ib * 4096;
    const __nv_bfloat16* __restrict__ khp = g_kh + (size_t)g * 65536;
    const __nv_bfloat16* __restrict__ vhp = g_vh + (size_t)g * 65536;

    if (t < 64) rs[t] = 0.0f;

    // stage Q hi
    #pragma unroll
    for (int i = 0; i < 2; i++) {
        int id = t + i * 256;
        int row = id >> 3, ch = id & 7;
        cpa16(smb + A_QH + row * 128 + ((ch ^ (row & 7)) << 4), qhp + row * 64 + ch * 8);
    }
    auto stage_kv = [&](int jb, int buf) {
        const uint32_t dst = smb + A_KV + buf * 32768;
        #pragma unroll
        for (int i = 0; i < 4; i++) {
            int id = t + i * 256;
            int row = id >> 3, ch = id & 7;
            uint32_t doff = row * 128 + ((ch ^ (row & 7)) << 4);
            cpa16(dst + doff, khp + (size_t)(jb * 128 + row) * 64 + ch * 8);
            cpa16(dst + 16384 + doff, vhp + (size_t)(jb * 128 + row) * 64 + ch * 8);
        }
        cpa_commit();
    };
    stage_kv(0, 0);

    float ev[2][8][4];
    #pragma unroll
    for (int a = 0; a < 2; a++)
        #pragma unroll
        for (int b = 0; b < 8; b++)
            #pragma unroll
            for (int c = 0; c < 4; c++) ev[a][b][c] = 0.0f;

    for (int jb = 0; jb < 8; jb++) {
        cpa_wait0();
        __syncthreads();
        if (jb < 7) stage_kv(jb + 1, (jb + 1) & 1);
        const uint32_t kb = smb + A_KV + (jb & 1) * 32768;
        const uint32_t vb = kb + 16384;

        // ---- QK^T: z (64 x 128), warp owns rows wm*32.., cols wn*32.. ----
        float acc[2][4][4];
        #pragma unroll
        for (int a = 0; a < 2; a++)
            #pragma unroll
            for (int b = 0; b < 4; b++)
                #pragma unroll
                for (int c = 0; c < 4; c++) acc[a][b][c] = 0.0f;

        #pragma unroll
        for (int kc = 0; kc < 4; kc++) {
            const int chunk = kc * 2 + (l >> 4);
            uint32_t qh_[2][4];
            #pragma unroll
            for (int mf = 0; mf < 2; mf++) {
                const int r = wm * 32 + mf * 16 + (l & 15);
                ldsm_x4(qh_[mf], smb + A_QH + r * 128 + ((chunk ^ (r & 7)) << 4));
            }
            #pragma unroll
            for (int nfp = 0; nfp < 2; nfp++) {
                const int rr = wn * 32 + nfp * 16 + (l & 15);
                uint32_t bh[4];
                ldsm_x4(bh, kb + rr * 128 + ((chunk ^ (rr & 7)) << 4));
                #pragma unroll
                for (int mf = 0; mf < 2; mf++) {
                    #pragma unroll
                    for (int nh = 0; nh < 2; nh++)
                        mma_bf16(acc[mf][nfp * 2 + nh], qh_[mf], bh[nh], bh[2 + nh]);
                }
            }
        }

        // ---- exp + E->smem + rowsums; keep packed bf16 as PV A-fragments --
        uint32_t pk[2][4][2];
        #pragma unroll
        for (int mf = 0; mf < 2; mf++) {
            const int rbase = wm * 32 + mf * 16 + (l >> 2);
            float s0 = 0.0f, s1 = 0.0f;
            #pragma unroll
            for (int nf = 0; nf < 4; nf++) {
                float* d = acc[mf][nf];
                const int col = jb * 128 + wn * 32 + nf * 8 + 2 * (l & 3);
                __nv_bfloat16 b0 = __float2bfloat16(__expf(fmaxf(d[0] * ATT_SCALE, 0.0f)));
                __nv_bfloat16 b1 = __float2bfloat16(__expf(fmaxf(d[1] * ATT_SCALE, 0.0f)));
                __nv_bfloat16 b2 = __float2bfloat16(__expf(fmaxf(d[2] * ATT_SCALE, 0.0f)));
                __nv_bfloat16 b3 = __float2bfloat16(__expf(fmaxf(d[3] * ATT_SCALE, 0.0f)));
                s0 += __bfloat162float(b0) + __bfloat162float(b1);
                s1 += __bfloat162float(b2) + __bfloat162float(b3);
                pk[mf][nf][0] = pack_bf2(b0, b1);
                pk[mf][nf][1] = pack_bf2(b2, b3);
                const int ch = col >> 3;
                const int off = (col & 7) * 2;
                *reinterpret_cast<uint32_t*>(smc + A_ESM + rbase * 2048 +
                    ((ch ^ (rbase & 7)) << 4) + off) = pk[mf][nf][0];
                *reinterpret_cast<uint32_t*>(smc + A_ESM + (rbase + 8) * 2048 +
                    ((ch ^ ((rbase + 8) & 7)) << 4) + off) = pk[mf][nf][1];
            }
            s0 += __shfl_xor_sync(0xffffffffu, s0, 1);
            s0 += __shfl_xor_sync(0xffffffffu, s0, 2);
            s1 += __shfl_xor_sync(0xffffffffu, s1, 1);
            s1 += __shfl_xor_sync(0xffffffffu, s1, 2);
            if ((l & 3) == 0) {
                atomicAdd(&rs[rbase], s0);
                atomicAdd(&rs[rbase + 8], s1);
            }
        }

        // ---- EV += E @ V over this warp's 32-col k-slice (2 k16 chunks) ---
        #pragma unroll
        for (int c = 0; c < 2; c++) {
            const int krow = wn * 32 + c * 16 + (l & 7) + (((l >> 3) & 1) << 3);
            uint32_t A0[4] = { pk[0][2 * c][0], pk[0][2 * c][1],
                               pk[0][2 * c + 1][0], pk[0][2 * c + 1][1] };
            uint32_t A1[4] = { pk[1][2 * c][0], pk[1][2 * c][1],
                               pk[1][2 * c + 1][0], pk[1][2 * c + 1][1] };
            #pragma unroll
            for (int nt = 0; nt < 4; nt++) {
                const int nch = nt * 2 + (l >> 4);
                uint32_t vh4[4];
                ldsm_x4_t(vh4, vb + krow * 128 + ((nch ^ (krow & 7)) << 4));
                mma_bf16(ev[0][2 * nt], A0, vh4[0], vh4[1]);
                mma_bf16(ev[0][2 * nt + 1], A0, vh4[2], vh4[3]);
                mma_bf16(ev[1][2 * nt], A1, vh4[0], vh4[1]);
                mma_bf16(ev[1][2 * nt + 1], A1, vh4[2], vh4[3]);
            }
        }
    }
    __syncthreads();   // rowsums complete; E smem stable; KV buffers free

    if (t < 64) rs[t] = 1.0f / rs[t];

    // ---- cross-warp EV reduce: write partials (row stride 272B, per wn) ---
    {
        char* red = smc + A_RED + wn * 17408;
        #pragma unroll
        for (int mf = 0; mf < 2; mf++) {
            const int row = wm * 32 + mf * 16 + (l >> 2);
            #pragma unroll
            for (int nf = 0; nf < 8; nf++) {
                const int col = nf * 8 + 2 * (l & 3);
                *reinterpret_cast<float2*>(red + row * 272 + col * 4) =
                    make_float2(ev[mf][nf][0], ev[mf][nf][1]);
                *reinterpret_cast<float2*>(red + (row + 8) * 272 + col * 4) =
                    make_float2(ev[mf][nf][2], ev[mf][nf][3]);
            }
        }
    }
    __syncthreads();

    // ---- reduce 4 partials, scale by rinv, write ctx ----------------------
    {
        const int r = t >> 2;
        const float ri = rs[r];
        float* __restrict__ Ch = g_ctx + (size_t)g * 65536 + ib * 4096;
        #pragma unroll
        for (int it = 0; it < 4; it++) {
            const int col = (t & 3) * 16 + it * 4;
            float4 s = make_float4(0.f, 0.f, 0.f, 0.f);
            #pragma unroll
            for (int p = 0; p < 4; p++) {
                float4 v = *reinterpret_cast<const float4*>(
                    smc + A_RED + p * 17408 + r * 272 + col * 4);
                s.x += v.x; s.y += v.y; s.z += v.z; s.w += v.w;
            }
            s.x *= ri; s.y *= ri; s.z *= ri; s.w *= ri;
            *reinterpret_cast<float4*>(Ch + (size_t)r * 64 + col) = s;
        }
    }

    // ---- colsums: cs_j = sum_i E[i][j] * rinv[i]  (4 cols per thread) -----
    {
        const int col = t * 4;
        const int ch = col >> 3;
        const int off = (col & 7) * 2;
        float c0 = 0.f, c1 = 0.f, c2 = 0.f, c3 = 0.f;
        #pragma unroll 4
        for (int i = 0; i < 64; i++) {
            const float ri = rs[i];
            uint2 u = *reinterpret_cast<const uint2*>(
                smc + A_ESM + i * 2048 + ((ch ^ (i & 7)) << 4) + off);
            float2 f01 = __bfloat1622float2(*reinterpret_cast<__nv_bfloat162*>(&u.x));
            float2 f23 = __bfloat1622float2(*reinterpret_cast<__nv_bfloat162*>(&u.y));
            c0 += ri * f01.x; c1 += ri * f01.y;
            c2 += ri * f23.x; c3 += ri * f23.y;
        }
        atomicAdd(&sums[g * 1024 + col + 0], c0);
        atomicAdd(&sums[g * 1024 + col + 1], c1);
        atomicAdd(&sums[g * 1024 + col + 2], c2);
        atomicAdd(&sums[g * 1024 + col + 3], c3);
    }
}

// ---------------------------------------------------------------------------
// Kernel 3: residual + LayerNorm
// ---------------------------------------------------------------------------
__global__ __launch_bounds__(256) void ln_kernel(
    const float* __restrict__ x,
    const float* __restrict__ gamma,
    const float* __restrict__ beta,
    float* __restrict__ out)
{
    const int row = blockIdx.x;
    const int t = threadIdx.x;
    const float* xr = x + (size_t)row * NTDIM;
    const float* cr = g_ctx + (size_t)row * NTDIM;

    float h[4];
    float s = 0.0f, sq = 0.0f;
    #pragma unroll
    for (int i = 0; i < 4; i++) {
        int idx = t + i * 256;
        h[i] = xr[idx] + cr[idx];
        s  += h[i];
        sq += h[i] * h[i];
    }
    #pragma unroll
    for (int off = 16; off; off >>= 1) {
        s  += __shfl_xor_sync(0xffffffffu, s,  off);
        sq += __shfl_xor_sync(0xffffffffu, sq, off);
    }
    __shared__ float rsum[8], rsq[8];
    int warp = t >> 5, lane = t & 31;
    if (lane == 0) { rsum[warp] = s; rsq[warp] = sq; }
    __syncthreads();
    float S = 0.0f, SQ = 0.0f;
    #pragma unroll
    for (int w = 0; w < 8; w++) { S += rsum[w]; SQ += rsq[w]; }
    float mean = S * (1.0f / NTDIM);
    float var  = SQ * (1.0f / NTDIM) - mean * mean;
    float inv  = rsqrtf(var + LNEPS);
    float* orow = out + (size_t)row * NTDIM;
    #pragma unroll
    for (int i = 0; i < 4; i++) {
        int idx = t + i * 256;
        orow[idx] = (h[i] - mean) * inv * gamma[idx] + beta[idx];
    }
}

// ---------------------------------------------------------------------------
extern "C" void kernel_launch(void* const* d_in, const int* in_sizes, int n_in,
                              void* d_out, int out_size)
{
    const float* x     = (const float*)d_in[0];
    const float* Wq    = (const float*)d_in[1];
    const float* bq    = (const float*)d_in[2];
    const float* Wk    = (const float*)d_in[3];
    const float* bk    = (const float*)d_in[4];
    const float* Wv    = (const float*)d_in[5];
    const float* bv    = (const float*)d_in[6];
    const float* gamma = (const float*)d_in[7];
    const float* beta  = (const float*)d_in[8];

    float* out  = (float*)d_out;
    float* sums = out + (size_t)M_ROWS * NTDIM;

    cudaFuncSetAttribute(qkv_mma_kernel,
                         cudaFuncAttributeMaxDynamicSharedMemorySize, QKV_SMEM);
    cudaFuncSetAttribute(attn_mma_kernel,
                         cudaFuncAttributeMaxDynamicSharedMemorySize, A_SMEM);

    zero_sums_kernel<<<256, 256>>>(sums);

    cvt_kernel<<<4096, 256>>>(x, 0);
    cvt_kernel<<<1024, 256>>>(Wq, 1);
    cvt_kernel<<<1024, 256>>>(Wk, 2);
    cvt_kernel<<<1024, 256>>>(Wv, 3);

    dim3 gq(8, 32, 3);
    qkv_mma_kernel<<<gq, 256, QKV_SMEM>>>(bq, bk, bv);

    dim3 ga(16, 64);
    attn_mma_kernel<<<ga, 256, A_SMEM>>>(sums);

    ln_kernel<<<M_ROWS, 256>>>(x, gamma, beta, out);
}

// round 8
// speedup vs baseline: 7.3596x; 1.0442x over previous
#include <cuda_runtime.h>
#include <cuda_fp16.h>
#include <cstdint>
#include <math.h>

// Problem constants
#define M_ROWS   4096      // B*S
#define NTDIM    1024
#define NGROUP   64        // B*heads
#define DPH      64
#define SEQ      1024
#define ATT_SCALE 0.03125f // 1024^-0.5
#define LNEPS    1e-5f

// Scratch (allocation-free rule: __device__ globals), all fp16
__device__ __half g_q[M_ROWS * NTDIM];
__device__ __half g_k[M_ROWS * NTDIM];
__device__ __half g_v[M_ROWS * NTDIM];
__device__ float  g_ctx[M_ROWS * NTDIM];
__device__ __half g_x[M_ROWS * NTDIM];
__device__ __half g_w[3 * NTDIM * NTDIM];

// ===========================================================================
// PTX helpers: mma.sync (HMMA f16) + ldmatrix + cp.async
// ===========================================================================
__device__ __forceinline__ uint32_t smem_u32(const void* p) {
    uint32_t a;
    asm("{ .reg .u64 t; cvta.to.shared.u64 t, %1; cvt.u32.u64 %0, t; }" : "=r"(a) : "l"(p));
    return a;
}
__device__ __forceinline__ void ldsm_x4(uint32_t* r, uint32_t addr) {
    asm volatile("ldmatrix.sync.aligned.m8n8.x4.shared.b16 {%0,%1,%2,%3}, [%4];"
                 : "=r"(r[0]), "=r"(r[1]), "=r"(r[2]), "=r"(r[3]) : "r"(addr));
}
__device__ __forceinline__ void ldsm_x4_t(uint32_t* r, uint32_t addr) {
    asm volatile("ldmatrix.sync.aligned.m8n8.x4.trans.shared.b16 {%0,%1,%2,%3}, [%4];"
                 : "=r"(r[0]), "=r"(r[1]), "=r"(r[2]), "=r"(r[3]) : "r"(addr));
}
__device__ __forceinline__ void mma_f16(float* d, const uint32_t* a,
                                        uint32_t b0, uint32_t b1) {
    asm volatile(
        "mma.sync.aligned.m16n8k16.row.col.f32.f16.f16.f32 "
        "{%0,%1,%2,%3}, {%4,%5,%6,%7}, {%8,%9}, {%0,%1,%2,%3};"
        : "+f"(d[0]), "+f"(d[1]), "+f"(d[2]), "+f"(d[3])
        : "r"(a[0]), "r"(a[1]), "r"(a[2]), "r"(a[3]), "r"(b0), "r"(b1));
}
__device__ __forceinline__ void cpa16(uint32_t dst, const void* src) {
    size_t gp;
    asm("cvta.to.global.u64 %0, %1;" : "=l"(gp) : "l"(src));
    asm volatile("cp.async.cg.shared.global [%0], [%1], 16;" :: "r"(dst), "l"(gp) : "memory");
}
__device__ __forceinline__ void cpa_commit() {
    asm volatile("cp.async.commit_group;" ::: "memory");
}
__device__ __forceinline__ void cpa_wait0() {
    asm volatile("cp.async.wait_group 0;" ::: "memory");
}
__device__ __forceinline__ void cpa_wait1() {
    asm volatile("cp.async.wait_group 1;" ::: "memory");
}
__device__ __forceinline__ uint32_t pack_h2(float lo, float hi) {
    __half2 v = __floats2half2_rn(lo, hi);
    return *reinterpret_cast<uint32_t*>(&v);
}

// ---------------------------------------------------------------------------
// Kernel 0: zero the at_sum_sum region of d_out
// ---------------------------------------------------------------------------
__global__ void zero_sums_kernel(float* __restrict__ sums) {
    sums[blockIdx.x * 256 + threadIdx.x] = 0.0f;
}

// ---------------------------------------------------------------------------
// Kernel 0b: fp32 -> fp16, one launch for x + Wq + Wk + Wv (7168 blocks)
// ---------------------------------------------------------------------------
__global__ __launch_bounds__(256) void cvt_all_kernel(
    const float* __restrict__ x, const float* __restrict__ wq,
    const float* __restrict__ wk, const float* __restrict__ wv)
{
    const int b = blockIdx.x;
    const float* src; __half* dst;
    if (b < 4096)      { src = x  + (size_t)b * 1024;          dst = g_x + (size_t)b * 1024; }
    else if (b < 5120) { src = wq + (size_t)(b - 4096) * 1024; dst = g_w + (size_t)(b - 4096) * 1024; }
    else if (b < 6144) { src = wk + (size_t)(b - 5120) * 1024; dst = g_w + 1048576 + (size_t)(b - 5120) * 1024; }
    else               { src = wv + (size_t)(b - 6144) * 1024; dst = g_w + 2097152 + (size_t)(b - 6144) * 1024; }
    const int i = threadIdx.x * 4;
    float4 v = *reinterpret_cast<const float4*>(src + i);
    uint2 u;
    u.x = pack_h2(v.x, v.y);
    u.y = pack_h2(v.z, v.w);
    *reinterpret_cast<uint2*>(dst + i) = u;
}

// ---------------------------------------------------------------------------
// Kernel 1: QKV projection via mma.sync f16, fp32 accum, 3-stage cp.async.
// C = X @ W^T + b -> fp16.  CTA tile 128x128, k-stage 64.
// ---------------------------------------------------------------------------
#define QST_AH 0
#define QST_BH 16384
#define QST_SZ 32768
#define QKV_SMEM (3 * QST_SZ)

__global__ __launch_bounds__(256) void qkv_mma_kernel(
    const float* __restrict__ bq, const float* __restrict__ bk, const float* __restrict__ bv)
{
    extern __shared__ char smc[];
    const uint32_t smb = smem_u32(smc);
    const int t = threadIdx.x;
    const int w = t >> 5;
    const int l = t & 31;
    const int z = blockIdx.z;
    const __half* __restrict__ Wh = g_w + (size_t)z * NTDIM * NTDIM;
    const float* bias = (z == 0) ? bq : (z == 1) ? bk : bv;
    __half* outh = (z == 0) ? g_q : (z == 1) ? g_k : g_v;
    const int m0 = blockIdx.y * 128;
    const int n0 = blockIdx.x * 128;
    const int wr0 = (w >> 1) * 32;
    const int wn0 = (w & 1) * 64;

    const int sr[4] = { (t + 0) >> 3, (t + 256) >> 3, (t + 512) >> 3, (t + 768) >> 3 };
    const int sc = t & 7;

    float acc[2][8][4];
    #pragma unroll
    for (int a = 0; a < 2; a++)
        #pragma unroll
        for (int b = 0; b < 8; b++)
            #pragma unroll
            for (int c = 0; c < 4; c++) acc[a][b][c] = 0.0f;

    auto issue_stage = [&](int s, int buf) {
        const int k0 = s * 64;
        const uint32_t sb = smb + buf * QST_SZ;
        #pragma unroll
        for (int i = 0; i < 4; i++) {
            const int r = sr[i];
            const uint32_t doff = r * 128 + (((sc ^ (r & 7)) << 4));
            cpa16(sb + QST_AH + doff, g_x + (size_t)(m0 + r) * NTDIM + k0 + sc * 8);
            cpa16(sb + QST_BH + doff, Wh + (size_t)(n0 + r) * NTDIM + k0 + sc * 8);
        }
        cpa_commit();
    };

    issue_stage(0, 0);
    issue_stage(1, 1);

    for (int s = 0; s < 16; s++) {
        if (s == 15) cpa_wait0(); else cpa_wait1();
        __syncthreads();
        if (s < 14) issue_stage(s + 2, (s + 2) % 3);
        const uint32_t bb = smb + (s % 3) * QST_SZ;

        #pragma unroll
        for (int kt = 0; kt < 4; kt++) {
            const int chunk = kt * 2 + (l >> 4);
            uint32_t ah[2][4];
            #pragma unroll
            for (int mf = 0; mf < 2; mf++) {
                const int r = wr0 + mf * 16 + (l & 15);
                ldsm_x4(ah[mf], bb + QST_AH + r * 128 + (((chunk ^ (r & 7)) << 4)));
            }
            #pragma unroll
            for (int nq = 0; nq < 4; nq++) {
                const int rr = wn0 + nq * 16 + (l & 15);
                uint32_t bh[4];
                ldsm_x4(bh, bb + QST_BH + rr * 128 + (((chunk ^ (rr & 7)) << 4)));
                #pragma unroll
                for (int mf = 0; mf < 2; mf++) {
                    #pragma unroll
                    for (int nh = 0; nh < 2; nh++)
                        mma_f16(acc[mf][nq * 2 + nh], ah[mf], bh[nh], bh[2 + nh]);
                }
            }
        }
    }

    // epilogue: acc + bias -> fp16
    const int lr = l >> 2;
    const int lc = (l & 3) * 2;
    #pragma unroll
    for (int mf = 0; mf < 2; mf++) {
        #pragma unroll
        for (int nf = 0; nf < 8; nf++) {
            const int col = n0 + wn0 + nf * 8 + lc;
            const int row = m0 + wr0 + mf * 16 + lr;
            const float* d = acc[mf][nf];
            *reinterpret_cast<uint32_t*>(outh + (size_t)row * NTDIM + col) =
                pack_h2(d[0] + bias[col], d[1] + bias[col + 1]);
            *reinterpret_cast<uint32_t*>(outh + (size_t)(row + 8) * NTDIM + col) =
                pack_h2(d[2] + bias[col], d[3] + bias[col + 1]);
        }
    }
}

// ---------------------------------------------------------------------------
// Kernel 2: attention, single fused pass.  CTA = 64 query rows x head-group.
// Per K/V block: z = Q K^T (MMA), E = exp(relu(z/32)) -> smem fp16 + register
// A-fragments, EV += E @ V (MMA, C-frag -> A-frag recycling), rowsums.
// Epilogue: ctx = diag(1/rs) * EV (4-warp smem reduce); colsums = E^T (1/rs).
// ---------------------------------------------------------------------------
#define A_ESM   0           // 64 x 2048B = 131072
#define A_QH    131072      // 8192
#define A_KV    139264      // 2 x (K 16384 + V 16384) = 65536 (loop only)
#define A_RED   139264      // 4 x 17408 = 69632 (epilogue, reuses KV)
#define A_RS    208896      // 64 floats
#define A_SMEM  209152

__global__ __launch_bounds__(256) void attn_mma_kernel(float* __restrict__ sums)
{
    extern __shared__ char smc[];
    const uint32_t smb = smem_u32(smc);
    float* rs = reinterpret_cast<float*>(smc + A_RS);

    const int ib = blockIdx.x;   // 0..15 (64-row block)
    const int g  = blockIdx.y;   // 0..63
    const int t  = threadIdx.x;
    const int w  = t >> 5;
    const int l  = t & 31;
    const int wm = w & 1;        // 2 row groups of 32
    const int wn = w >> 1;       // 4 col (k-slice) groups of 32

    const __half* __restrict__ qhp = g_q + (size_t)g * 65536 + ib * 4096;
    const __half* __restrict__ khp = g_k + (size_t)g * 65536;
    const __half* __restrict__ vhp = g_v + (size_t)g * 65536;

    if (t < 64) rs[t] = 0.0f;

    // stage Q
    #pragma unroll
    for (int i = 0; i < 2; i++) {
        int id = t + i * 256;
        int row = id >> 3, ch = id & 7;
        cpa16(smb + A_QH + row * 128 + ((ch ^ (row & 7)) << 4), qhp + row * 64 + ch * 8);
    }
    auto stage_kv = [&](int jb, int buf) {
        const uint32_t dst = smb + A_KV + buf * 32768;
        #pragma unroll
        for (int i = 0; i < 4; i++) {
            int id = t + i * 256;
            int row = id >> 3, ch = id & 7;
            uint32_t doff = row * 128 + ((ch ^ (row & 7)) << 4);
            cpa16(dst + doff, khp + (size_t)(jb * 128 + row) * 64 + ch * 8);
            cpa16(dst + 16384 + doff, vhp + (size_t)(jb * 128 + row) * 64 + ch * 8);
        }
        cpa_commit();
    };
    stage_kv(0, 0);

    float ev[2][8][4];
    #pragma unroll
    for (int a = 0; a < 2; a++)
        #pragma unroll
        for (int b = 0; b < 8; b++)
            #pragma unroll
            for (int c = 0; c < 4; c++) ev[a][b][c] = 0.0f;

    uint32_t qf[4][2][4];   // hoisted Q fragments (loaded at jb==0)

    for (int jb = 0; jb < 8; jb++) {
        cpa_wait0();
        __syncthreads();
        if (jb < 7) stage_kv(jb + 1, (jb + 1) & 1);
        const uint32_t kb = smb + A_KV + (jb & 1) * 32768;
        const uint32_t vb = kb + 16384;

        if (jb == 0) {
            #pragma unroll
            for (int kc = 0; kc < 4; kc++) {
                const int chunk = kc * 2 + (l >> 4);
                #pragma unroll
                for (int mf = 0; mf < 2; mf++) {
                    const int r = wm * 32 + mf * 16 + (l & 15);
                    ldsm_x4(qf[kc][mf], smb + A_QH + r * 128 + ((chunk ^ (r & 7)) << 4));
                }
            }
        }

        // ---- QK^T: z (64 x 128), warp owns rows wm*32.., cols wn*32.. ----
        float acc[2][4][4];
        #pragma unroll
        for (int a = 0; a < 2; a++)
            #pragma unroll
            for (int b = 0; b < 4; b++)
                #pragma unroll
                for (int c = 0; c < 4; c++) acc[a][b][c] = 0.0f;

        #pragma unroll
        for (int kc = 0; kc < 4; kc++) {
            const int chunk = kc * 2 + (l >> 4);
            #pragma unroll
            for (int nfp = 0; nfp < 2; nfp++) {
                const int rr = wn * 32 + nfp * 16 + (l & 15);
                uint32_t bh[4];
                ldsm_x4(bh, kb + rr * 128 + ((chunk ^ (rr & 7)) << 4));
                #pragma unroll
                for (int mf = 0; mf < 2; mf++) {
                    #pragma unroll
                    for (int nh = 0; nh < 2; nh++)
                        mma_f16(acc[mf][nfp * 2 + nh], qf[kc][mf], bh[nh], bh[2 + nh]);
                }
            }
        }

        // ---- exp + E->smem (fp16) + rowsums; keep packed fp16 as PV A-frags
        uint32_t pk[2][4][2];
        #pragma unroll
        for (int mf = 0; mf < 2; mf++) {
            const int rbase = wm * 32 + mf * 16 + (l >> 2);
            float s0 = 0.0f, s1 = 0.0f;
            #pragma unroll
            for (int nf = 0; nf < 4; nf++) {
                float* d = acc[mf][nf];
                const int col = jb * 128 + wn * 32 + nf * 8 + 2 * (l & 3);
                float e0 = __expf(fmaxf(d[0] * ATT_SCALE, 0.0f));
                float e1 = __expf(fmaxf(d[1] * ATT_SCALE, 0.0f));
                float e2 = __expf(fmaxf(d[2] * ATT_SCALE, 0.0f));
                float e3 = __expf(fmaxf(d[3] * ATT_SCALE, 0.0f));
                s0 += e0 + e1;
                s1 += e2 + e3;
                pk[mf][nf][0] = pack_h2(e0, e1);
                pk[mf][nf][1] = pack_h2(e2, e3);
                const int ch = col >> 3;
                const int off = (col & 7) * 2;
                *reinterpret_cast<uint32_t*>(smc + A_ESM + rbase * 2048 +
                    ((ch ^ (rbase & 7)) << 4) + off) = pk[mf][nf][0];
                *reinterpret_cast<uint32_t*>(smc + A_ESM + (rbase + 8) * 2048 +
                    ((ch ^ ((rbase + 8) & 7)) << 4) + off) = pk[mf][nf][1];
            }
            s0 += __shfl_xor_sync(0xffffffffu, s0, 1);
            s0 += __shfl_xor_sync(0xffffffffu, s0, 2);
            s1 += __shfl_xor_sync(0xffffffffu, s1, 1);
            s1 += __shfl_xor_sync(0xffffffffu, s1, 2);
            if ((l & 3) == 0) {
                atomicAdd(&rs[rbase], s0);
                atomicAdd(&rs[rbase + 8], s1);
            }
        }

        // ---- EV += E @ V over this warp's 32-col k-slice (2 k16 chunks) ---
        #pragma unroll
        for (int c = 0; c < 2; c++) {
            const int krow = wn * 32 + c * 16 + (l & 7) + (((l >> 3) & 1) << 3);
            uint32_t A0[4] = { pk[0][2 * c][0], pk[0][2 * c][1],
                               pk[0][2 * c + 1][0], pk[0][2 * c + 1][1] };
            uint32_t A1[4] = { pk[1][2 * c][0], pk[1][2 * c][1],
                               pk[1][2 * c + 1][0], pk[1][2 * c + 1][1] };
            #pragma unroll
            for (int nt = 0; nt < 4; nt++) {
                const int nch = nt * 2 + (l >> 4);
                uint32_t vh4[4];
                ldsm_x4_t(vh4, vb + krow * 128 + ((nch ^ (krow & 7)) << 4));
                mma_f16(ev[0][2 * nt], A0, vh4[0], vh4[1]);
                mma_f16(ev[0][2 * nt + 1], A0, vh4[2], vh4[3]);
                mma_f16(ev[1][2 * nt], A1, vh4[0], vh4[1]);
                mma_f16(ev[1][2 * nt + 1], A1, vh4[2], vh4[3]);
            }
        }
    }
    __syncthreads();   // rowsums complete; E smem stable; KV buffers free

    if (t < 64) rs[t] = 1.0f / rs[t];

    // ---- cross-warp EV reduce: write partials (row stride 272B, per wn) ---
    {
        char* red = smc + A_RED + wn * 17408;
        #pragma unroll
        for (int mf = 0; mf < 2; mf++) {
            const int row = wm * 32 + mf * 16 + (l >> 2);
            #pragma unroll
            for (int nf = 0; nf < 8; nf++) {
                const int col = nf * 8 + 2 * (l & 3);
                *reinterpret_cast<float2*>(red + row * 272 + col * 4) =
                    make_float2(ev[mf][nf][0], ev[mf][nf][1]);
                *reinterpret_cast<float2*>(red + (row + 8) * 272 + col * 4) =
                    make_float2(ev[mf][nf][2], ev[mf][nf][3]);
            }
        }
    }
    __syncthreads();

    // ---- reduce 4 partials, scale by rinv, write ctx ----------------------
    {
        const int r = t >> 2;
        const float ri = rs[r];
        float* __restrict__ Ch = g_ctx + (size_t)g * 65536 + ib * 4096;
        #pragma unroll
        for (int it = 0; it < 4; it++) {
            const int col = (t & 3) * 16 + it * 4;
            float4 s = make_float4(0.f, 0.f, 0.f, 0.f);
            #pragma unroll
            for (int p = 0; p < 4; p++) {
                float4 v = *reinterpret_cast<const float4*>(
                    smc + A_RED + p * 17408 + r * 272 + col * 4);
                s.x += v.x; s.y += v.y; s.z += v.z; s.w += v.w;
            }
            s.x *= ri; s.y *= ri; s.z *= ri; s.w *= ri;
            *reinterpret_cast<float4*>(Ch + (size_t)r * 64 + col) = s;
        }
    }

    // ---- colsums: cs_j = sum_i E[i][j] * rinv[i]  (4 cols per thread) -----
    {
        const int col = t * 4;
        const int ch = col >> 3;
        const int off = (col & 7) * 2;
        float c0 = 0.f, c1 = 0.f, c2 = 0.f, c3 = 0.f;
        #pragma unroll 4
        for (int i = 0; i < 64; i++) {
            const float ri = rs[i];
            uint2 u = *reinterpret_cast<const uint2*>(
                smc + A_ESM + i * 2048 + ((ch ^ (i & 7)) << 4) + off);
            float2 f01 = __half22float2(*reinterpret_cast<__half2*>(&u.x));
            float2 f23 = __half22float2(*reinterpret_cast<__half2*>(&u.y));
            c0 += ri * f01.x; c1 += ri * f01.y;
            c2 += ri * f23.x; c3 += ri * f23.y;
        }
        atomicAdd(&sums[g * 1024 + col + 0], c0);
        atomicAdd(&sums[g * 1024 + col + 1], c1);
        atomicAdd(&sums[g * 1024 + col + 2], c2);
        atomicAdd(&sums[g * 1024 + col + 3], c3);
    }
}

// ---------------------------------------------------------------------------
// Kernel 3: residual + LayerNorm
// ---------------------------------------------------------------------------
__global__ __launch_bounds__(256) void ln_kernel(
    const float* __restrict__ x,
    const float* __restrict__ gamma,
    const float* __restrict__ beta,
    float* __restrict__ out)
{
    const int row = blockIdx.x;
    const int t = threadIdx.x;
    const float* xr = x + (size_t)row * NTDIM;
    const float* cr = g_ctx + (size_t)row * NTDIM;

    float h[4];
    float s = 0.0f, sq = 0.0f;
    #pragma unroll
    for (int i = 0; i < 4; i++) {
        int idx = t + i * 256;
        h[i] = xr[idx] + cr[idx];
        s  += h[i];
        sq += h[i] * h[i];
    }
    #pragma unroll
    for (int off = 16; off; off >>= 1) {
        s  += __shfl_xor_sync(0xffffffffu, s,  off);
        sq += __shfl_xor_sync(0xffffffffu, sq, off);
    }
    __shared__ float rsum[8], rsq[8];
    int warp = t >> 5, lane = t & 31;
    if (lane == 0) { rsum[warp] = s; rsq[warp] = sq; }
    __syncthreads();
    float S = 0.0f, SQ = 0.0f;
    #pragma unroll
    for (int w = 0; w < 8; w++) { S += rsum[w]; SQ += rsq[w]; }
    float mean = S * (1.0f / NTDIM);
    float var  = SQ * (1.0f / NTDIM) - mean * mean;
    float inv  = rsqrtf(var + LNEPS);
    float* orow = out + (size_t)row * NTDIM;
    #pragma unroll
    for (int i = 0; i < 4; i++) {
        int idx = t + i * 256;
        orow[idx] = (h[i] - mean) * inv * gamma[idx] + beta[idx];
    }
}

// ---------------------------------------------------------------------------
extern "C" void kernel_launch(void* const* d_in, const int* in_sizes, int n_in,
                              void* d_out, int out_size)
{
    const float* x     = (const float*)d_in[0];
    const float* Wq    = (const float*)d_in[1];
    const float* bq    = (const float*)d_in[2];
    const float* Wk    = (const float*)d_in[3];
    const float* bk    = (const float*)d_in[4];
    const float* Wv    = (const float*)d_in[5];
    const float* bv    = (const float*)d_in[6];
    const float* gamma = (const float*)d_in[7];
    const float* beta  = (const float*)d_in[8];

    float* out  = (float*)d_out;
    float* sums = out + (size_t)M_ROWS * NTDIM;

    cudaFuncSetAttribute(qkv_mma_kernel,
                         cudaFuncAttributeMaxDynamicSharedMemorySize, QKV_SMEM);
    cudaFuncSetAttribute(attn_mma_kernel,
                         cudaFuncAttributeMaxDynamicSharedMemorySize, A_SMEM);

    zero_sums_kernel<<<256, 256>>>(sums);

    cvt_all_kernel<<<7168, 256>>>(x, Wq, Wk, Wv);

    dim3 gq(8, 32, 3);
    qkv_mma_kernel<<<gq, 256, QKV_SMEM>>>(bq, bk, bv);

    dim3 ga(16, 64);
    attn_mma_kernel<<<ga, 256, A_SMEM>>>(sums);

    ln_kernel<<<M_ROWS, 256>>>(x, gamma, beta, out);
}